// round 4
// baseline (speedup 1.0000x reference)
#include <cuda_runtime.h>
#include <cstdint>

typedef unsigned long long u64;

#define NTHREADS 256
#define NPTS_BLK 512   // 2 points per thread

// ---------------------------------------------------------------------------
// Device scratch: transposed weights Wt[l][k][j] = W_l[j][k]  (6 layers 64x64)
// ---------------------------------------------------------------------------
__device__ __align__(16) float g_Wt[6 * 64 * 64];

__global__ void transpose_w_kernel(const float* __restrict__ W0, const float* __restrict__ W1,
                                   const float* __restrict__ W2, const float* __restrict__ W3,
                                   const float* __restrict__ W4, const float* __restrict__ W5) {
    int i = blockIdx.x * blockDim.x + threadIdx.x;
    if (i >= 6 * 4096) return;
    int l = i >> 12, rr = i & 4095, j = rr >> 6, k = rr & 63;
    const float* W;
    switch (l) {
        case 0: W = W0; break; case 1: W = W1; break; case 2: W = W2; break;
        case 3: W = W3; break; case 4: W = W4; break; default: W = W5; break;
    }
    g_Wt[(l << 12) + (k << 6) + j] = W[(j << 6) + k];
}

// ---------------------------------------------------------------------------
// Packed f32x2 helpers (FFMA2: 2x fp32 throughput on sm_103a vs 3-reg FFMA)
// ---------------------------------------------------------------------------
__device__ __forceinline__ void fma2(u64& d, u64 a, u64 b) {
    asm("fma.rn.f32x2 %0, %1, %2, %0;" : "+l"(d) : "l"(a), "l"(b));
}
__device__ __forceinline__ u64 pack2(float x, float y) {
    u64 r; asm("mov.b64 %0, {%1, %2};" : "=l"(r) : "f"(x), "f"(y)); return r;
}
__device__ __forceinline__ void unpack2(u64 v, float& x, float& y) {
    asm("mov.b64 {%0, %1}, %2;" : "=f"(x), "=f"(y) : "l"(v));
}

// ---------------------------------------------------------------------------
// Fused encode + 7-layer MLP. One block = 512 points. Activations live in a
// per-thread-private shared column (no inter-thread sharing -> NO barriers in
// the layer loop). All transposed weights resident in shared for the block.
// Shared = 64*512*4 (A) + 6*4096*4 (Wt) + 192*4 (W6) = 230144 B  (1 block/SM)
// ---------------------------------------------------------------------------
__global__ __launch_bounds__(NTHREADS, 1)
void nrc_mlp_kernel(const float* __restrict__ gp,    const float* __restrict__ gwi,
                    const float* __restrict__ gn,    const float* __restrict__ galpha,
                    const float* __restrict__ gbeta, const float* __restrict__ gr,
                    const float* __restrict__ gW6,   float* __restrict__ gout, int B)
{
    extern __shared__ float smem[];
    float* sA  = smem;                    // [64][NPTS_BLK]
    float* sWt = smem + 64 * NPTS_BLK;    // [6][64][64]  (k-major rows, j contiguous)
    float* sW6 = sWt + 6 * 4096;          // [3][64]

    const int tid = threadIdx.x;

    // ---- stage all weights into shared (issued early; consumed after barrier)
    {
        const float4* src = (const float4*)g_Wt;
        float4*       dst = (float4*)sWt;
        #pragma unroll
        for (int i = 0; i < 24; i++)               // 24*256 = 6144 float4 = 24576 floats
            dst[tid + i * NTHREADS] = src[tid + i * NTHREADS];
        if (tid < 192) sW6[tid] = gW6[tid];
    }

    const int col  = 2 * tid;
    const int base = blockIdx.x * NPTS_BLK + col;
    float ab[6];                                   // (alpha+beta) for both points

    // ---- encoding: 64 features per point, written to this thread's A column
    #pragma unroll
    for (int q = 0; q < 2; q++) {
        const int id = base + q;
        float* Acol = sA + col + q;                // row stride = NPTS_BLK
        if (id < B) {
            const float PI = 3.14159265358979323846f;
            const int id3 = id * 3;
            // frequency embedding: 36 features (3 dims x 6 freqs x sin/cos)
            float pd0 = gp[id3], pd1 = gp[id3 + 1], pd2 = gp[id3 + 2];
            float pds[3] = {pd0, pd1, pd2};
            #pragma unroll
            for (int d = 0; d < 3; d++) {
                float a = PI * pds[d];
                #pragma unroll
                for (int fq = 0; fq < 6; fq++) {
                    float s, c;
                    sincosf(a, &s, &c);
                    Acol[(d * 12 + fq)     * NPTS_BLK] = s;
                    Acol[(d * 12 + 6 + fq) * NPTS_BLK] = c;
                    a = a + a;                      // exact x2 each octave
                }
            }
            // spherical one-blob for wi and n: 8 features each
            #pragma unroll
            for (int which = 0; which < 2; which++) {
                const float* src3 = (which == 0) ? gwi : gn;
                const int off = 36 + which * 8;
                float x = src3[id3], y = src3[id3 + 1], z = src3[id3 + 2];
                float nn = sqrtf(x * x + y * y + z * z) + 1e-8f;
                float u  = atan2f(y, x) * 0.15915494309189535f + 0.5f;   // 1/(2pi)
                float zn = z / nn;
                zn = fminf(fmaxf(zn, -1.0f + 1e-6f), 1.0f - 1e-6f);
                float v  = acosf(zn) * 0.3183098861837907f;              // 1/pi
                #pragma unroll
                for (int i = 0; i < 4; i++) {
                    float c  = 0.125f + 0.25f * (float)i;
                    float t0 = (u - c) * 4.0f;
                    float t1 = (v - c) * 4.0f;
                    Acol[(off + i)     * NPTS_BLK] = expf(-0.5f * t0 * t0);
                    Acol[(off + 4 + i) * NPTS_BLK] = expf(-0.5f * t1 * t1);
                }
            }
            // roughness one-blob: 4 features
            {
                float xr = 1.0f - expf(-gr[id]);
                #pragma unroll
                for (int i = 0; i < 4; i++) {
                    float c = 0.125f + 0.25f * (float)i;
                    float t = (xr - c) * 4.0f;
                    Acol[(52 + i) * NPTS_BLK] = expf(-0.5f * t * t);
                }
            }
            // alpha(3), beta(3), ones(2)
            float a0 = galpha[id3], a1 = galpha[id3 + 1], a2 = galpha[id3 + 2];
            float b0 = gbeta[id3],  b1 = gbeta[id3 + 1],  b2 = gbeta[id3 + 2];
            Acol[56 * NPTS_BLK] = a0; Acol[57 * NPTS_BLK] = a1; Acol[58 * NPTS_BLK] = a2;
            Acol[59 * NPTS_BLK] = b0; Acol[60 * NPTS_BLK] = b1; Acol[61 * NPTS_BLK] = b2;
            Acol[62 * NPTS_BLK] = 1.0f; Acol[63 * NPTS_BLK] = 1.0f;
            ab[q * 3 + 0] = a0 + b0; ab[q * 3 + 1] = a1 + b1; ab[q * 3 + 2] = a2 + b2;
        } else {
            #pragma unroll
            for (int j = 0; j < 64; j++) Acol[j * NPTS_BLK] = 0.0f;
            ab[q * 3 + 0] = ab[q * 3 + 1] = ab[q * 3 + 2] = 0.0f;
        }
    }

    __syncthreads();   // weights visible; A columns are private (this is the ONLY barrier)

    // ---- 6 hidden layers, 64->64 + ReLU
    // acc pairs over OUTPUT dim j: acc[m] holds outputs (2m, 2m+1) of one point.
    // Weight pairs come straight out of LDS.128 (Wt row k is j-contiguous): no repack.
    for (int l = 0; l < 6; l++) {
        u64 acc0[32], acc1[32];
        #pragma unroll
        for (int m = 0; m < 32; m++) { acc0[m] = 0ull; acc1[m] = 0ull; }

        const float* wrow = sWt + l * 4096;
        #pragma unroll 4
        for (int k = 0; k < 64; k++) {
            float2 h = *(const float2*)(sA + k * NPTS_BLK + col);
            u64 h0 = pack2(h.x, h.x);
            u64 h1 = pack2(h.y, h.y);
            const ulonglong2* w4 = (const ulonglong2*)(wrow + k * 64);
            #pragma unroll
            for (int m4 = 0; m4 < 16; m4++) {
                ulonglong2 w = w4[m4];                 // LDS.128, warp-broadcast
                fma2(acc0[2 * m4],     w.x, h0);
                fma2(acc0[2 * m4 + 1], w.y, h0);
                fma2(acc1[2 * m4],     w.x, h1);
                fma2(acc1[2 * m4 + 1], w.y, h1);
            }
        }
        // ReLU + writeback to own column (no barrier needed: column is private)
        #pragma unroll
        for (int m = 0; m < 32; m++) {
            float a0lo, a0hi, a1lo, a1hi;
            unpack2(acc0[m], a0lo, a0hi);
            unpack2(acc1[m], a1lo, a1hi);
            *(float2*)(sA + (2 * m)     * NPTS_BLK + col) =
                make_float2(fmaxf(a0lo, 0.0f), fmaxf(a1lo, 0.0f));
            *(float2*)(sA + (2 * m + 1) * NPTS_BLK + col) =
                make_float2(fmaxf(a0hi, 0.0f), fmaxf(a1hi, 0.0f));
        }
    }

    // ---- final layer 64->3, scale by (alpha+beta), store
    float o0[3] = {0.f, 0.f, 0.f};
    float o1[3] = {0.f, 0.f, 0.f};
    #pragma unroll 4
    for (int k = 0; k < 64; k++) {
        float2 h = *(const float2*)(sA + k * NPTS_BLK + col);
        #pragma unroll
        for (int i = 0; i < 3; i++) {
            float w = sW6[i * 64 + k];
            o0[i] += w * h.x;
            o1[i] += w * h.y;
        }
    }
    if (base < B) {
        #pragma unroll
        for (int i = 0; i < 3; i++) gout[base * 3 + i] = o0[i] * ab[i];
    }
    if (base + 1 < B) {
        #pragma unroll
        for (int i = 0; i < 3; i++) gout[(base + 1) * 3 + i] = o1[i] * ab[3 + i];
    }
}

// ---------------------------------------------------------------------------
// Launch: inputs in metadata order p, wi, n, alpha, beta, r, W0..W6
// ---------------------------------------------------------------------------
extern "C" void kernel_launch(void* const* d_in, const int* in_sizes, int n_in,
                              void* d_out, int out_size) {
    const float* p     = (const float*)d_in[0];
    const float* wi    = (const float*)d_in[1];
    const float* nrm   = (const float*)d_in[2];
    const float* alpha = (const float*)d_in[3];
    const float* beta  = (const float*)d_in[4];
    const float* r     = (const float*)d_in[5];
    const float* W0    = (const float*)d_in[6];
    const float* W1    = (const float*)d_in[7];
    const float* W2    = (const float*)d_in[8];
    const float* W3    = (const float*)d_in[9];
    const float* W4    = (const float*)d_in[10];
    const float* W5    = (const float*)d_in[11];
    const float* W6    = (const float*)d_in[12];

    const int B = in_sizes[0] / 3;

    transpose_w_kernel<<<(6 * 4096 + 255) / 256, 256>>>(W0, W1, W2, W3, W4, W5);

    const size_t smem_bytes = (size_t)(64 * NPTS_BLK + 6 * 4096 + 192) * sizeof(float);
    cudaFuncSetAttribute(nrc_mlp_kernel,
                         cudaFuncAttributeMaxDynamicSharedMemorySize, (int)smem_bytes);

    const int grid = (B + NPTS_BLK - 1) / NPTS_BLK;
    nrc_mlp_kernel<<<grid, NTHREADS, smem_bytes>>>(p, wi, nrm, alpha, beta, r, W6,
                                                   (float*)d_out, B);
}

// round 6
// speedup vs baseline: 2.0193x; 2.0193x over previous
#include <cuda_runtime.h>
#include <cuda_bf16.h>
#include <cstdint>

#define NTHREADS 256
#define CTA_PTS  256
#define WSTRIDE  72                 // bf16 elems per weight/staging row (64 + 8 pad)
#define ROWB     (WSTRIDE * 2)      // 144 bytes per row
#define WMAT_B   (64 * ROWB)        // 9216 B per 64x64 bf16 matrix

// ---- SMEM layout (bytes) --------------------------------------------------
#define OFF_W    0                  // 12 matrices (6 layers x hi/lo) = 110592 B
#define OFF_A    (12 * WMAT_B)      // A staging hi [256][72] bf16 = 36864 B
#define A_BYTES  (CTA_PTS * ROWB)
#define OFF_ALO  (OFF_A + A_BYTES)  // A staging lo
#define OFF_W6   (OFF_ALO + A_BYTES)// 192 floats
#define SM_TOTAL (OFF_W6 + 768)     // 185088 B

// ---- Device scratch: pre-split, padded weights ----------------------------
__device__ __align__(16) unsigned char g_Wb[12 * WMAT_B];

__global__ void prep_weights(const float* __restrict__ W0, const float* __restrict__ W1,
                             const float* __restrict__ W2, const float* __restrict__ W3,
                             const float* __restrict__ W4, const float* __restrict__ W5) {
    int i = blockIdx.x * blockDim.x + threadIdx.x;
    if (i >= 6 * 4096) return;
    int l = i >> 12, j = (i >> 6) & 63, k = i & 63;
    const float* W;
    switch (l) {
        case 0: W = W0; break; case 1: W = W1; break; case 2: W = W2; break;
        case 3: W = W3; break; case 4: W = W4; break; default: W = W5; break;
    }
    float w = W[j * 64 + k];
    __nv_bfloat16 hi = __float2bfloat16(w);
    __nv_bfloat16 lo = __float2bfloat16(w - __bfloat162float(hi));
    __nv_bfloat16* g = (__nv_bfloat16*)g_Wb;
    g[((2 * l)     * 64 + j) * WSTRIDE + k] = hi;
    g[((2 * l + 1) * 64 + j) * WSTRIDE + k] = lo;
}

// ---- warp-level MMA helpers (baseline PTX, no sm_103a features) -----------
__device__ __forceinline__ uint32_t smem_u32(const void* p) {
    uint32_t a;
    asm("{ .reg .u64 t; cvta.to.shared.u64 t, %1; cvt.u32.u64 %0, t; }" : "=r"(a) : "l"(p));
    return a;
}
__device__ __forceinline__ void ldsm4(uint32_t& r0, uint32_t& r1, uint32_t& r2, uint32_t& r3,
                                      uint32_t addr) {
    asm volatile("ldmatrix.sync.aligned.m8n8.x4.shared.b16 {%0,%1,%2,%3}, [%4];"
                 : "=r"(r0), "=r"(r1), "=r"(r2), "=r"(r3) : "r"(addr));
}
__device__ __forceinline__ void mma16816(float* c, const uint32_t* a, uint32_t b0, uint32_t b1) {
    asm volatile("mma.sync.aligned.m16n8k16.row.col.f32.bf16.bf16.f32 "
                 "{%0,%1,%2,%3}, {%4,%5,%6,%7}, {%8,%9}, {%0,%1,%2,%3};"
                 : "+f"(c[0]), "+f"(c[1]), "+f"(c[2]), "+f"(c[3])
                 : "r"(a[0]), "r"(a[1]), "r"(a[2]), "r"(a[3]), "r"(b0), "r"(b1));
}
// pack two fp32 -> bf16x2 (lo -> lower 16 bits = even-k element)
__device__ __forceinline__ uint32_t packbf(float lo, float hi) {
    __nv_bfloat162 t = __floats2bfloat162_rn(lo, hi);   // .x = lo = lower half
    return *(uint32_t*)&t;
}

// write one feature (hi + residual-lo bf16) into staging
__device__ __forceinline__ void put_feat(char* sm, int row, int k, float x) {
    __nv_bfloat16 h = __float2bfloat16(x);
    __nv_bfloat16 lo = __float2bfloat16(x - __bfloat162float(h));
    *(__nv_bfloat16*)(sm + OFF_A   + row * ROWB + k * 2) = h;
    *(__nv_bfloat16*)(sm + OFF_ALO + row * ROWB + k * 2) = lo;
}

// ---------------------------------------------------------------------------
// Fully-fused: encode -> 6x split-bf16 HMMA layers (activations in registers,
// C-frag == next A-frag layout) -> exact fp32 final layer. 256 thr = 8 warps,
// warp owns m=32 rows (2 m16 tiles). ONE barrier total.
// ---------------------------------------------------------------------------
__global__ __launch_bounds__(NTHREADS, 1)
void nrc_mma_kernel(const float* __restrict__ gp,    const float* __restrict__ gwi,
                    const float* __restrict__ gn,    const float* __restrict__ galpha,
                    const float* __restrict__ gbeta, const float* __restrict__ gr,
                    const float* __restrict__ gW6,   float* __restrict__ gout, int B)
{
    extern __shared__ __align__(16) char smem[];
    const int tid  = threadIdx.x;
    const int lane = tid & 31;
    const int warp = tid >> 5;

    // ---- stage pre-split weights (110592 B) + W6 into SMEM
    {
        const float4* src = (const float4*)g_Wb;
        float4*       dst = (float4*)(smem + OFF_W);
        for (int i = tid; i < 12 * WMAT_B / 16; i += NTHREADS) dst[i] = src[i];
        if (tid < 192) ((float*)(smem + OFF_W6))[tid] = gW6[tid];
    }

    // ---- encode one point -> staging rows (bf16 hi/lo, padded stride)
    const int id  = blockIdx.x * CTA_PTS + tid;
    const int idc = (id < B) ? id : (B - 1);
    const int id3 = idc * 3;
    {
        const float PI = 3.14159265358979323846f;
        float pds[3] = {gp[id3], gp[id3 + 1], gp[id3 + 2]};
        #pragma unroll
        for (int d = 0; d < 3; d++) {
            float a = PI * pds[d];
            #pragma unroll
            for (int fq = 0; fq < 6; fq++) {
                float s, c;
                sincosf(a, &s, &c);
                put_feat(smem, tid, d * 12 + fq,     s);
                put_feat(smem, tid, d * 12 + 6 + fq, c);
                a = a + a;                       // exact x2 per octave
            }
        }
        #pragma unroll
        for (int which = 0; which < 2; which++) {
            const float* s3 = which ? gn : gwi;
            const int off = 36 + which * 8;
            float x = s3[id3], y = s3[id3 + 1], z = s3[id3 + 2];
            float nn = sqrtf(x * x + y * y + z * z) + 1e-8f;
            float u  = atan2f(y, x) * 0.15915494309189535f + 0.5f;
            float zn = z / nn;
            zn = fminf(fmaxf(zn, -1.0f + 1e-6f), 1.0f - 1e-6f);
            float v  = acosf(zn) * 0.3183098861837907f;
            #pragma unroll
            for (int i = 0; i < 4; i++) {
                float c  = 0.125f + 0.25f * (float)i;
                float t0 = (u - c) * 4.0f;
                float t1 = (v - c) * 4.0f;
                put_feat(smem, tid, off + i,     expf(-0.5f * t0 * t0));
                put_feat(smem, tid, off + 4 + i, expf(-0.5f * t1 * t1));
            }
        }
        {
            float xr = 1.0f - expf(-gr[idc]);
            #pragma unroll
            for (int i = 0; i < 4; i++) {
                float c = 0.125f + 0.25f * (float)i;
                float t = (xr - c) * 4.0f;
                put_feat(smem, tid, 52 + i, expf(-0.5f * t * t));
            }
        }
        put_feat(smem, tid, 56, galpha[id3]);
        put_feat(smem, tid, 57, galpha[id3 + 1]);
        put_feat(smem, tid, 58, galpha[id3 + 2]);
        put_feat(smem, tid, 59, gbeta[id3]);
        put_feat(smem, tid, 60, gbeta[id3 + 1]);
        put_feat(smem, tid, 61, gbeta[id3 + 2]);
        put_feat(smem, tid, 62, 1.0f);
        put_feat(smem, tid, 63, 1.0f);
    }

    __syncthreads();   // weights + staging visible; everything after is warp-local

    // ---- per-lane ldmatrix address components
    const uint32_t smb  = smem_u32(smem);
    const int rit = lane & 7;
    const uint32_t laneA = ((uint32_t)(rit + ((lane >> 3) & 1) * 8) * ROWB) + ((lane >> 4) & 1) * 16;
    const uint32_t laneB = ((uint32_t)(rit + ((lane >> 4) & 1) * 8) * ROWB) + ((lane >> 3) & 1) * 16;
    const int wrb = warp * 32;                    // warp's first row (point)

    // ---- load layer-0 A fragments (hi + lo) from staging
    uint32_t Ah[4][8], Al[4][8];                  // [k-block][m-tile*4 + reg]
    {
        uint32_t ab = smb + OFF_A + (uint32_t)wrb * ROWB + laneA;
        #pragma unroll
        for (int kb = 0; kb < 4; kb++)
            #pragma unroll
            for (int mt = 0; mt < 2; mt++) {
                uint32_t a = ab + mt * 16 * ROWB + kb * 32;
                ldsm4(Ah[kb][4 * mt], Ah[kb][4 * mt + 1], Ah[kb][4 * mt + 2], Ah[kb][4 * mt + 3], a);
                ldsm4(Al[kb][4 * mt], Al[kb][4 * mt + 1], Al[kb][4 * mt + 2], Al[kb][4 * mt + 3],
                      a + A_BYTES);
            }
    }

    float C[8][8];                                // [n-block][m-tile*4 + reg]
    #pragma unroll 1
    for (int l = 0; l < 6; l++) {
        #pragma unroll
        for (int nb = 0; nb < 8; nb++)
            #pragma unroll
            for (int i = 0; i < 8; i++) C[nb][i] = 0.0f;

        // 3 passes: Ahi*Whi, Ahi*Wlo, Alo*Whi  (fp32 accumulate)
        #pragma unroll
        for (int pass = 0; pass < 3; pass++) {
            const uint32_t (*A)[8] = (pass == 2) ? Al : Ah;
            uint32_t wb = smb + OFF_W + (uint32_t)(l * 2 + (pass == 1)) * WMAT_B + laneB;
            #pragma unroll
            for (int kb = 0; kb < 4; kb++) {
                #pragma unroll
                for (int np = 0; np < 4; np++) {
                    uint32_t r0, r1, r2, r3;      // b-frags: nblk 2np (r0,r1), 2np+1 (r2,r3)
                    ldsm4(r0, r1, r2, r3, wb + (uint32_t)np * (16 * ROWB) + kb * 32);
                    #pragma unroll
                    for (int mt = 0; mt < 2; mt++) {
                        mma16816(&C[2 * np][4 * mt],     &A[kb][4 * mt], r0, r1);
                        mma16816(&C[2 * np + 1][4 * mt], &A[kb][4 * mt], r2, r3);
                    }
                }
            }
        }

        // ReLU
        #pragma unroll
        for (int nb = 0; nb < 8; nb++)
            #pragma unroll
            for (int i = 0; i < 8; i++) C[nb][i] = fmaxf(C[nb][i], 0.0f);

        // register re-split: C-frag (two n8 blocks) == next A-frag (one k16 block)
        if (l < 5) {
            #pragma unroll
            for (int kb = 0; kb < 4; kb++)
                #pragma unroll
                for (int mt = 0; mt < 2; mt++) {
                    const float* c0 = &C[2 * kb][4 * mt];
                    const float* c1 = &C[2 * kb + 1][4 * mt];
                    #pragma unroll
                    for (int h = 0; h < 2; h++) {          // h=0: rows g, h=1: rows g+8
                        float e0 = c0[2 * h], o0 = c0[2 * h + 1];
                        float e1 = c1[2 * h], o1 = c1[2 * h + 1];
                        uint32_t p0 = packbf(e0, o0);
                        uint32_t p1 = packbf(e1, o1);
                        Ah[kb][4 * mt + h]     = p0;
                        Ah[kb][4 * mt + 2 + h] = p1;
                        float r0 = e0 - __uint_as_float(p0 << 16);
                        float r1 = o0 - __uint_as_float(p0 & 0xFFFF0000u);
                        float r2 = e1 - __uint_as_float(p1 << 16);
                        float r3 = o1 - __uint_as_float(p1 & 0xFFFF0000u);
                        Al[kb][4 * mt + h]     = packbf(r0, r1);
                        Al[kb][4 * mt + 2 + h] = packbf(r2, r3);
                    }
                }
        }
    }

    // ---- final layer 64->3 in exact fp32 from C fragments
    const float* W6s = (const float*)(smem + OFF_W6);
    const int g   = lane >> 2;
    const int tig = lane & 3;
    float o[4][3];
    #pragma unroll
    for (int s = 0; s < 4; s++) { o[s][0] = 0.f; o[s][1] = 0.f; o[s][2] = 0.f; }

    #pragma unroll
    for (int nb = 0; nb < 8; nb++) {
        const int k0 = nb * 8 + 2 * tig;
        #pragma unroll
        for (int mt = 0; mt < 2; mt++) {
            float v0 = C[nb][4 * mt + 0], v1 = C[nb][4 * mt + 1];   // row g + 16mt
            float v2 = C[nb][4 * mt + 2], v3 = C[nb][4 * mt + 3];   // row g + 16mt + 8
            #pragma unroll
            for (int i = 0; i < 3; i++) {
                float w0 = W6s[i * 64 + k0], w1 = W6s[i * 64 + k0 + 1];
                o[2 * mt][i]     += v0 * w0 + v1 * w1;
                o[2 * mt + 1][i] += v2 * w0 + v3 * w1;
            }
        }
    }
    #pragma unroll
    for (int s = 0; s < 4; s++)
        #pragma unroll
        for (int i = 0; i < 3; i++) {
            o[s][i] += __shfl_xor_sync(0xFFFFFFFFu, o[s][i], 1);
            o[s][i] += __shfl_xor_sync(0xFFFFFFFFu, o[s][i], 2);
        }

    if (tig == 0) {
        #pragma unroll
        for (int s = 0; s < 4; s++) {
            int row = wrb + g + 16 * (s >> 1) + 8 * (s & 1);
            int idp = blockIdx.x * CTA_PTS + row;
            if (idp < B) {
                int i3 = idp * 3;
                #pragma unroll
                for (int i = 0; i < 3; i++)
                    gout[i3 + i] = o[s][i] * (galpha[i3 + i] + gbeta[i3 + i]);
            }
        }
    }
}

// ---------------------------------------------------------------------------
extern "C" void kernel_launch(void* const* d_in, const int* in_sizes, int n_in,
                              void* d_out, int out_size) {
    const float* p     = (const float*)d_in[0];
    const float* wi    = (const float*)d_in[1];
    const float* nrm   = (const float*)d_in[2];
    const float* alpha = (const float*)d_in[3];
    const float* beta  = (const float*)d_in[4];
    const float* r     = (const float*)d_in[5];
    const float* W0    = (const float*)d_in[6];
    const float* W1    = (const float*)d_in[7];
    const float* W2    = (const float*)d_in[8];
    const float* W3    = (const float*)d_in[9];
    const float* W4    = (const float*)d_in[10];
    const float* W5    = (const float*)d_in[11];
    const float* W6    = (const float*)d_in[12];

    const int B = in_sizes[0] / 3;

    prep_weights<<<(6 * 4096 + 255) / 256, 256>>>(W0, W1, W2, W3, W4, W5);

    cudaFuncSetAttribute(nrc_mma_kernel,
                         cudaFuncAttributeMaxDynamicSharedMemorySize, SM_TOTAL);
    const int grid = (B + CTA_PTS - 1) / CTA_PTS;
    nrc_mma_kernel<<<grid, NTHREADS, SM_TOTAL>>>(p, wi, nrm, alpha, beta, r, W6,
                                                 (float*)d_out, B);
}

// round 7
// speedup vs baseline: 2.3247x; 1.1512x over previous
#include <cuda_runtime.h>
#include <cuda_bf16.h>
#include <cstdint>

#define NTHREADS 512                // 16 warps, m=16 per warp
#define CTA_PTS  256
#define WSTRIDE  72                 // bf16 elems per weight/staging row (64 + 8 pad)
#define ROWB     (WSTRIDE * 2)      // 144 bytes per row
#define WMAT_B   (64 * ROWB)        // 9216 B per 64x64 bf16 matrix

// ---- SMEM layout (bytes) --------------------------------------------------
#define OFF_W    0                  // 12 matrices (6 layers x hi/lo) = 110592 B
#define OFF_A    (12 * WMAT_B)      // A staging hi [256][72] bf16 = 36864 B
#define A_BYTES  (CTA_PTS * ROWB)
#define OFF_ALO  (OFF_A + A_BYTES)  // A staging lo
#define OFF_W6   (OFF_ALO + A_BYTES)// 192 floats
#define SM_TOTAL (OFF_W6 + 768)     // 185088 B

// ---- Device scratch: pre-split, padded weights ----------------------------
__device__ __align__(16) unsigned char g_Wb[12 * WMAT_B];

__global__ void prep_weights(const float* __restrict__ W0, const float* __restrict__ W1,
                             const float* __restrict__ W2, const float* __restrict__ W3,
                             const float* __restrict__ W4, const float* __restrict__ W5) {
    int i = blockIdx.x * blockDim.x + threadIdx.x;
    if (i >= 6 * 4096) return;
    int l = i >> 12, j = (i >> 6) & 63, k = i & 63;
    const float* W;
    switch (l) {
        case 0: W = W0; break; case 1: W = W1; break; case 2: W = W2; break;
        case 3: W = W3; break; case 4: W = W4; break; default: W = W5; break;
    }
    float w = W[j * 64 + k];
    __nv_bfloat16 hi = __float2bfloat16(w);
    __nv_bfloat16 lo = __float2bfloat16(w - __bfloat162float(hi));
    __nv_bfloat16* g = (__nv_bfloat16*)g_Wb;
    g[((2 * l)     * 64 + j) * WSTRIDE + k] = hi;   // Whi matrix
    g[((2 * l + 1) * 64 + j) * WSTRIDE + k] = lo;   // Wlo matrix
}

// ---- warp-level MMA helpers (baseline PTX, no sm_103a features) -----------
__device__ __forceinline__ uint32_t smem_u32(const void* p) {
    uint32_t a;
    asm("{ .reg .u64 t; cvta.to.shared.u64 t, %1; cvt.u32.u64 %0, t; }" : "=r"(a) : "l"(p));
    return a;
}
__device__ __forceinline__ void ldsm4(uint32_t& r0, uint32_t& r1, uint32_t& r2, uint32_t& r3,
                                      uint32_t addr) {
    asm volatile("ldmatrix.sync.aligned.m8n8.x4.shared.b16 {%0,%1,%2,%3}, [%4];"
                 : "=r"(r0), "=r"(r1), "=r"(r2), "=r"(r3) : "r"(addr));
}
__device__ __forceinline__ void mma16816(float* c, const uint32_t* a, uint32_t b0, uint32_t b1) {
    asm volatile("mma.sync.aligned.m16n8k16.row.col.f32.bf16.bf16.f32 "
                 "{%0,%1,%2,%3}, {%4,%5,%6,%7}, {%8,%9}, {%0,%1,%2,%3};"
                 : "+f"(c[0]), "+f"(c[1]), "+f"(c[2]), "+f"(c[3])
                 : "r"(a[0]), "r"(a[1]), "r"(a[2]), "r"(a[3]), "r"(b0), "r"(b1));
}
__device__ __forceinline__ uint32_t packbf(float lo, float hi) {
    __nv_bfloat162 t = __floats2bfloat162_rn(lo, hi);   // .x = lower 16 bits
    return *(uint32_t*)&t;
}
__device__ __forceinline__ void put_feat(char* sm, int row, int k, float x) {
    __nv_bfloat16 h = __float2bfloat16(x);
    __nv_bfloat16 lo = __float2bfloat16(x - __bfloat162float(h));
    *(__nv_bfloat16*)(sm + OFF_A   + row * ROWB + k * 2) = h;
    *(__nv_bfloat16*)(sm + OFF_ALO + row * ROWB + k * 2) = lo;
}

// ---------------------------------------------------------------------------
// Fully-fused: encode -> 6x split-bf16 HMMA layers (activations stay in
// registers, C-frag == next A-frag layout) -> exact fp32 final layer.
// 512 thr = 16 warps, warp owns m=16 rows. Whi fragments loaded ONCE per
// layer and shared by the Ahi and Alo passes. ONE barrier total.
// ---------------------------------------------------------------------------
__global__ __launch_bounds__(NTHREADS, 1)
void nrc_mma_kernel(const float* __restrict__ gp,    const float* __restrict__ gwi,
                    const float* __restrict__ gn,    const float* __restrict__ galpha,
                    const float* __restrict__ gbeta, const float* __restrict__ gr,
                    const float* __restrict__ gW6,   float* __restrict__ gout, int B)
{
    extern __shared__ __align__(16) char smem[];
    const int tid  = threadIdx.x;
    const int lane = tid & 31;
    const int warp = tid >> 5;

    if (tid >= 256) {
        // ---- threads 256..511: stage pre-split weights (110592 B) + W6
        const int t = tid - 256;
        const float4* src = (const float4*)g_Wb;
        float4*       dst = (float4*)(smem + OFF_W);
        #pragma unroll
        for (int j = 0; j < 27; j++)                  // 27*256 = 6912 float4
            dst[t + j * 256] = src[t + j * 256];
        if (t < 192) ((float*)(smem + OFF_W6))[t] = gW6[t];
    } else {
        // ---- threads 0..255: encode one point -> staging rows (bf16 hi/lo)
        const int id  = blockIdx.x * CTA_PTS + tid;
        const int idc = (id < B) ? id : (B - 1);
        const int id3 = idc * 3;
        const float PI = 3.14159265358979323846f;
        float pds[3] = {gp[id3], gp[id3 + 1], gp[id3 + 2]};
        #pragma unroll
        for (int d = 0; d < 3; d++) {
            float a = PI * pds[d];
            #pragma unroll
            for (int fq = 0; fq < 6; fq++) {
                float s, c;
                sincosf(a, &s, &c);
                put_feat(smem, tid, d * 12 + fq,     s);
                put_feat(smem, tid, d * 12 + 6 + fq, c);
                a = a + a;                            // exact x2 per octave
            }
        }
        #pragma unroll
        for (int which = 0; which < 2; which++) {
            const float* s3 = which ? gn : gwi;
            const int off = 36 + which * 8;
            float x = s3[id3], y = s3[id3 + 1], z = s3[id3 + 2];
            float nn = sqrtf(x * x + y * y + z * z) + 1e-8f;
            float u  = atan2f(y, x) * 0.15915494309189535f + 0.5f;
            float zn = z / nn;
            zn = fminf(fmaxf(zn, -1.0f + 1e-6f), 1.0f - 1e-6f);
            float v  = acosf(zn) * 0.3183098861837907f;
            #pragma unroll
            for (int i = 0; i < 4; i++) {
                float c  = 0.125f + 0.25f * (float)i;
                float t0 = (u - c) * 4.0f;
                float t1 = (v - c) * 4.0f;
                put_feat(smem, tid, off + i,     expf(-0.5f * t0 * t0));
                put_feat(smem, tid, off + 4 + i, expf(-0.5f * t1 * t1));
            }
        }
        {
            float xr = 1.0f - expf(-gr[idc]);
            #pragma unroll
            for (int i = 0; i < 4; i++) {
                float c = 0.125f + 0.25f * (float)i;
                float t = (xr - c) * 4.0f;
                put_feat(smem, tid, 52 + i, expf(-0.5f * t * t));
            }
        }
        put_feat(smem, tid, 56, galpha[id3]);
        put_feat(smem, tid, 57, galpha[id3 + 1]);
        put_feat(smem, tid, 58, galpha[id3 + 2]);
        put_feat(smem, tid, 59, gbeta[id3]);
        put_feat(smem, tid, 60, gbeta[id3 + 1]);
        put_feat(smem, tid, 61, gbeta[id3 + 2]);
        put_feat(smem, tid, 62, 1.0f);
        put_feat(smem, tid, 63, 1.0f);
    }

    __syncthreads();   // weights + staging visible; everything after is warp-local

    // ---- per-lane ldmatrix address components
    const uint32_t smb  = smem_u32(smem);
    const int rit = lane & 7;
    const uint32_t laneA = ((uint32_t)(rit + ((lane >> 3) & 1) * 8) * ROWB) + ((lane >> 4) & 1) * 16;
    const uint32_t laneB = ((uint32_t)(rit + ((lane >> 4) & 1) * 8) * ROWB) + ((lane >> 3) & 1) * 16;
    const int wrb = warp * 16;                    // warp's first row (point)

    // ---- load layer-0 A fragments (hi + lo) from staging
    uint32_t Ah[4][4], Al[4][4];                  // [k-block][frag reg]
    {
        uint32_t ab = smb + OFF_A + (uint32_t)wrb * ROWB + laneA;
        #pragma unroll
        for (int kb = 0; kb < 4; kb++) {
            uint32_t a = ab + kb * 32;
            ldsm4(Ah[kb][0], Ah[kb][1], Ah[kb][2], Ah[kb][3], a);
            ldsm4(Al[kb][0], Al[kb][1], Al[kb][2], Al[kb][3], a + A_BYTES);
        }
    }

    float C[8][4];                                // [n-block][frag reg]
    #pragma unroll 1
    for (int l = 0; l < 6; l++) {
        #pragma unroll
        for (int nb = 0; nb < 8; nb++)
            #pragma unroll
            for (int i = 0; i < 4; i++) C[nb][i] = 0.0f;

        // Whi fragment loaded ONCE, feeds Ahi*Whi AND Alo*Whi; then Wlo -> Ahi*Wlo
        const uint32_t whi = smb + OFF_W + (uint32_t)(2 * l)     * WMAT_B + laneB;
        const uint32_t wlo = smb + OFF_W + (uint32_t)(2 * l + 1) * WMAT_B + laneB;
        #pragma unroll
        for (int kb = 0; kb < 4; kb++) {
            #pragma unroll
            for (int np = 0; np < 4; np++) {
                const uint32_t boff = (uint32_t)np * (16 * ROWB) + kb * 32;
                uint32_t h0, h1, h2, h3;
                ldsm4(h0, h1, h2, h3, whi + boff);
                mma16816(C[2 * np],     Ah[kb], h0, h1);
                mma16816(C[2 * np + 1], Ah[kb], h2, h3);
                mma16816(C[2 * np],     Al[kb], h0, h1);
                mma16816(C[2 * np + 1], Al[kb], h2, h3);
                uint32_t g0, g1, g2, g3;
                ldsm4(g0, g1, g2, g3, wlo + boff);
                mma16816(C[2 * np],     Ah[kb], g0, g1);
                mma16816(C[2 * np + 1], Ah[kb], g2, g3);
            }
        }

        // ReLU
        #pragma unroll
        for (int nb = 0; nb < 8; nb++)
            #pragma unroll
            for (int i = 0; i < 4; i++) C[nb][i] = fmaxf(C[nb][i], 0.0f);

        // register re-split: C-frag (two n8 blocks) == next A-frag (one k16 block)
        if (l < 5) {
            #pragma unroll
            for (int kb = 0; kb < 4; kb++) {
                const float* c0 = C[2 * kb];
                const float* c1 = C[2 * kb + 1];
                #pragma unroll
                for (int h = 0; h < 2; h++) {          // h=0: row g, h=1: row g+8
                    float e0 = c0[2 * h], o0 = c0[2 * h + 1];
                    float e1 = c1[2 * h], o1 = c1[2 * h + 1];
                    uint32_t p0 = packbf(e0, o0);
                    uint32_t p1 = packbf(e1, o1);
                    Ah[kb][h]     = p0;
                    Ah[kb][2 + h] = p1;
                    float r0 = e0 - __uint_as_float(p0 << 16);
                    float r1 = o0 - __uint_as_float(p0 & 0xFFFF0000u);
                    float r2 = e1 - __uint_as_float(p1 << 16);
                    float r3 = o1 - __uint_as_float(p1 & 0xFFFF0000u);
                    Al[kb][h]     = packbf(r0, r1);
                    Al[kb][2 + h] = packbf(r2, r3);
                }
            }
        }
    }

    // ---- final layer 64->3 in exact fp32 from C fragments
    const float* W6s = (const float*)(smem + OFF_W6);
    const int g   = lane >> 2;
    const int tig = lane & 3;
    float o[2][3];
    #pragma unroll
    for (int s = 0; s < 2; s++) { o[s][0] = 0.f; o[s][1] = 0.f; o[s][2] = 0.f; }

    #pragma unroll
    for (int nb = 0; nb < 8; nb++) {
        const int k0 = nb * 8 + 2 * tig;
        float v0 = C[nb][0], v1 = C[nb][1];       // row g
        float v2 = C[nb][2], v3 = C[nb][3];       // row g + 8
        #pragma unroll
        for (int i = 0; i < 3; i++) {
            float w0 = W6s[i * 64 + k0], w1 = W6s[i * 64 + k0 + 1];
            o[0][i] += v0 * w0 + v1 * w1;
            o[1][i] += v2 * w0 + v3 * w1;
        }
    }
    #pragma unroll
    for (int s = 0; s < 2; s++)
        #pragma unroll
        for (int i = 0; i < 3; i++) {
            o[s][i] += __shfl_xor_sync(0xFFFFFFFFu, o[s][i], 1);
            o[s][i] += __shfl_xor_sync(0xFFFFFFFFu, o[s][i], 2);
        }

    if (tig == 0) {
        #pragma unroll
        for (int s = 0; s < 2; s++) {
            int row = wrb + g + 8 * s;
            int idp = blockIdx.x * CTA_PTS + row;
            if (idp < B) {
                int i3 = idp * 3;
                #pragma unroll
                for (int i = 0; i < 3; i++)
                    gout[i3 + i] = o[s][i] * (galpha[i3 + i] + gbeta[i3 + i]);
            }
        }
    }
}

// ---------------------------------------------------------------------------
extern "C" void kernel_launch(void* const* d_in, const int* in_sizes, int n_in,
                              void* d_out, int out_size) {
    const float* p     = (const float*)d_in[0];
    const float* wi    = (const float*)d_in[1];
    const float* nrm   = (const float*)d_in[2];
    const float* alpha = (const float*)d_in[3];
    const float* beta  = (const float*)d_in[4];
    const float* r     = (const float*)d_in[5];
    const float* W0    = (const float*)d_in[6];
    const float* W1    = (const float*)d_in[7];
    const float* W2    = (const float*)d_in[8];
    const float* W3    = (const float*)d_in[9];
    const float* W4    = (const float*)d_in[10];
    const float* W5    = (const float*)d_in[11];
    const float* W6    = (const float*)d_in[12];

    const int B = in_sizes[0] / 3;

    prep_weights<<<(6 * 4096 + 255) / 256, 256>>>(W0, W1, W2, W3, W4, W5);

    cudaFuncSetAttribute(nrc_mma_kernel,
                         cudaFuncAttributeMaxDynamicSharedMemorySize, SM_TOTAL);
    const int grid = (B + CTA_PTS - 1) / CTA_PTS;
    nrc_mma_kernel<<<grid, NTHREADS, SM_TOTAL>>>(p, wi, nrm, alpha, beta, r, W6,
                                                 (float*)d_out, B);
}

// round 8
// speedup vs baseline: 3.0176x; 1.2980x over previous
#include <cuda_runtime.h>
#include <cuda_fp16.h>
#include <cstdint>

#define NTHREADS 512                // 16 warps, m=16 per warp
#define CTA_PTS  256
#define WSTRIDE  72                 // fp16 elems per weight/staging row (64 + 8 pad)
#define ROWB     (WSTRIDE * 2)      // 144 bytes per row
#define WMAT_B   (64 * ROWB)        // 9216 B per 64x64 fp16 matrix

// ---- SMEM layout (bytes) --------------------------------------------------
#define OFF_W    0                  // 6 fp16 weight matrices = 55296 B
#define OFF_A    (6 * WMAT_B)       // A staging hi [256][72] fp16 = 36864 B
#define A_BYTES  (CTA_PTS * ROWB)
#define OFF_ALO  (OFF_A + A_BYTES)  // A staging lo
#define OFF_W6   (OFF_ALO + A_BYTES)// 192 floats
#define SM_TOTAL (OFF_W6 + 768)     // 129792 B

// ---- Device scratch: fp16 padded weights ----------------------------------
__device__ __align__(16) unsigned char g_Wb[6 * WMAT_B];

__global__ void prep_weights(const float* __restrict__ W0, const float* __restrict__ W1,
                             const float* __restrict__ W2, const float* __restrict__ W3,
                             const float* __restrict__ W4, const float* __restrict__ W5) {
    int i = blockIdx.x * blockDim.x + threadIdx.x;
    if (i >= 6 * 4096) return;
    int l = i >> 12, j = (i >> 6) & 63, k = i & 63;
    const float* W;
    switch (l) {
        case 0: W = W0; break; case 1: W = W1; break; case 2: W = W2; break;
        case 3: W = W3; break; case 4: W = W4; break; default: W = W5; break;
    }
    ((__half*)g_Wb)[(l * 64 + j) * WSTRIDE + k] = __float2half_rn(W[j * 64 + k]);
}

// ---- warp-level MMA helpers (baseline PTX, no sm_103a features) -----------
__device__ __forceinline__ uint32_t smem_u32(const void* p) {
    uint32_t a;
    asm("{ .reg .u64 t; cvta.to.shared.u64 t, %1; cvt.u32.u64 %0, t; }" : "=r"(a) : "l"(p));
    return a;
}
__device__ __forceinline__ void ldsm4(uint32_t& r0, uint32_t& r1, uint32_t& r2, uint32_t& r3,
                                      uint32_t addr) {
    asm volatile("ldmatrix.sync.aligned.m8n8.x4.shared.b16 {%0,%1,%2,%3}, [%4];"
                 : "=r"(r0), "=r"(r1), "=r"(r2), "=r"(r3) : "r"(addr));
}
__device__ __forceinline__ void mma16816(float* c, const uint32_t* a, uint32_t b0, uint32_t b1) {
    asm volatile("mma.sync.aligned.m16n8k16.row.col.f32.f16.f16.f32 "
                 "{%0,%1,%2,%3}, {%4,%5,%6,%7}, {%8,%9}, {%0,%1,%2,%3};"
                 : "+f"(c[0]), "+f"(c[1]), "+f"(c[2]), "+f"(c[3])
                 : "r"(a[0]), "r"(a[1]), "r"(a[2]), "r"(a[3]), "r"(b0), "r"(b1));
}
__device__ __forceinline__ uint32_t packh(float lo, float hi) {
    __half2 t = __floats2half2_rn(lo, hi);              // .x = lower 16 bits
    return *(uint32_t*)&t;
}
__device__ __forceinline__ void put_feat(char* sm, int row, int k, float x) {
    __half h = __float2half_rn(x);
    __half l = __float2half_rn(x - __half2float(h));
    *(__half*)(sm + OFF_A   + row * ROWB + k * 2) = h;
    *(__half*)(sm + OFF_ALO + row * ROWB + k * 2) = l;
}

// ---------------------------------------------------------------------------
// Fully-fused: encode -> 6 layers of 2-pass split-fp16 HMMA (A = Ahi + Alo,
// W single fp16; activations stay in registers, C-frag == next A-frag layout)
// -> exact fp32 final layer. 512 thr = 16 warps, warp owns m=16 rows.
// Each W fragment is loaded ONCE and feeds 4 MMAs. ONE barrier total.
// ---------------------------------------------------------------------------
__global__ __launch_bounds__(NTHREADS, 1)
void nrc_mma_kernel(const float* __restrict__ gp,    const float* __restrict__ gwi,
                    const float* __restrict__ gn,    const float* __restrict__ galpha,
                    const float* __restrict__ gbeta, const float* __restrict__ gr,
                    const float* __restrict__ gW6,   float* __restrict__ gout, int B)
{
    extern __shared__ __align__(16) char smem[];
    const int tid  = threadIdx.x;
    const int lane = tid & 31;
    const int warp = tid >> 5;

    if (tid >= 256) {
        // ---- threads 256..511: stage fp16 weights (55296 B) + W6
        const int t = tid - 256;
        const float4* src = (const float4*)g_Wb;
        float4*       dst = (float4*)(smem + OFF_W);
        #pragma unroll
        for (int j = 0; j < 13; j++)                  // 13*256 = 3328
            dst[t + j * 256] = src[t + j * 256];
        if (t < 3456 - 3328) dst[t + 3328] = src[t + 3328];
        if (t < 192) ((float*)(smem + OFF_W6))[t] = gW6[t];
    } else {
        // ---- threads 0..255: encode one point -> staging rows (fp16 hi/lo)
        const int id  = blockIdx.x * CTA_PTS + tid;
        const int idc = (id < B) ? id : (B - 1);
        const int id3 = idc * 3;
        const float PI = 3.14159265358979323846f;
        float pds[3] = {gp[id3], gp[id3 + 1], gp[id3 + 2]};
        #pragma unroll
        for (int d = 0; d < 3; d++) {
            float a = PI * pds[d];
            #pragma unroll
            for (int fq = 0; fq < 6; fq++) {
                float s, c;
                sincosf(a, &s, &c);
                put_feat(smem, tid, d * 12 + fq,     s);
                put_feat(smem, tid, d * 12 + 6 + fq, c);
                a = a + a;                            // exact x2 per octave
            }
        }
        #pragma unroll
        for (int which = 0; which < 2; which++) {
            const float* s3 = which ? gn : gwi;
            const int off = 36 + which * 8;
            float x = s3[id3], y = s3[id3 + 1], z = s3[id3 + 2];
            float nn = sqrtf(x * x + y * y + z * z) + 1e-8f;
            float u  = atan2f(y, x) * 0.15915494309189535f + 0.5f;
            float zn = z / nn;
            zn = fminf(fmaxf(zn, -1.0f + 1e-6f), 1.0f - 1e-6f);
            float v  = acosf(zn) * 0.3183098861837907f;
            #pragma unroll
            for (int i = 0; i < 4; i++) {
                float c  = 0.125f + 0.25f * (float)i;
                float t0 = (u - c) * 4.0f;
                float t1 = (v - c) * 4.0f;
                put_feat(smem, tid, off + i,     expf(-0.5f * t0 * t0));
                put_feat(smem, tid, off + 4 + i, expf(-0.5f * t1 * t1));
            }
        }
        {
            float xr = 1.0f - expf(-gr[idc]);
            #pragma unroll
            for (int i = 0; i < 4; i++) {
                float c = 0.125f + 0.25f * (float)i;
                float t = (xr - c) * 4.0f;
                put_feat(smem, tid, 52 + i, expf(-0.5f * t * t));
            }
        }
        put_feat(smem, tid, 56, galpha[id3]);
        put_feat(smem, tid, 57, galpha[id3 + 1]);
        put_feat(smem, tid, 58, galpha[id3 + 2]);
        put_feat(smem, tid, 59, gbeta[id3]);
        put_feat(smem, tid, 60, gbeta[id3 + 1]);
        put_feat(smem, tid, 61, gbeta[id3 + 2]);
        put_feat(smem, tid, 62, 1.0f);
        put_feat(smem, tid, 63, 1.0f);
    }

    __syncthreads();   // weights + staging visible; everything after is warp-local

    // ---- per-lane ldmatrix address components
    const uint32_t smb  = smem_u32(smem);
    const int rit = lane & 7;
    const uint32_t laneA = ((uint32_t)(rit + ((lane >> 3) & 1) * 8) * ROWB) + ((lane >> 4) & 1) * 16;
    const uint32_t laneB = ((uint32_t)(rit + ((lane >> 4) & 1) * 8) * ROWB) + ((lane >> 3) & 1) * 16;
    const int wrb = warp * 16;                    // warp's first row (point)

    // ---- load layer-0 A fragments (hi + lo) from staging
    uint32_t Ah[4][4], Al[4][4];                  // [k-block][frag reg]
    {
        uint32_t ab = smb + OFF_A + (uint32_t)wrb * ROWB + laneA;
        #pragma unroll
        for (int kb = 0; kb < 4; kb++) {
            uint32_t a = ab + kb * 32;
            ldsm4(Ah[kb][0], Ah[kb][1], Ah[kb][2], Ah[kb][3], a);
            ldsm4(Al[kb][0], Al[kb][1], Al[kb][2], Al[kb][3], a + A_BYTES);
        }
    }

    float C[8][4];                                // [n-block][frag reg]
    #pragma unroll 1
    for (int l = 0; l < 6; l++) {
        #pragma unroll
        for (int nb = 0; nb < 8; nb++)
            #pragma unroll
            for (int i = 0; i < 4; i++) C[nb][i] = 0.0f;

        // W fragment loaded ONCE, feeds Ahi*W and Alo*W (fp32 accumulate)
        const uint32_t wmat = smb + OFF_W + (uint32_t)l * WMAT_B + laneB;
        #pragma unroll
        for (int kb = 0; kb < 4; kb++) {
            #pragma unroll
            for (int np = 0; np < 4; np++) {
                uint32_t h0, h1, h2, h3;
                ldsm4(h0, h1, h2, h3, wmat + (uint32_t)np * (16 * ROWB) + kb * 32);
                mma16816(C[2 * np],     Ah[kb], h0, h1);
                mma16816(C[2 * np + 1], Ah[kb], h2, h3);
                mma16816(C[2 * np],     Al[kb], h0, h1);
                mma16816(C[2 * np + 1], Al[kb], h2, h3);
            }
        }

        // ReLU
        #pragma unroll
        for (int nb = 0; nb < 8; nb++)
            #pragma unroll
            for (int i = 0; i < 4; i++) C[nb][i] = fmaxf(C[nb][i], 0.0f);

        // register re-split: C-frag (two n8 blocks) == next A-frag (one k16 block)
        if (l < 5) {
            #pragma unroll
            for (int kb = 0; kb < 4; kb++) {
                const float* c0 = C[2 * kb];
                const float* c1 = C[2 * kb + 1];
                #pragma unroll
                for (int h = 0; h < 2; h++) {          // h=0: row g, h=1: row g+8
                    float e0 = c0[2 * h], o0 = c0[2 * h + 1];
                    float e1 = c1[2 * h], o1 = c1[2 * h + 1];
                    uint32_t p0 = packh(e0, o0);
                    uint32_t p1 = packh(e1, o1);
                    Ah[kb][h]     = p0;
                    Ah[kb][2 + h] = p1;
                    float2 f0 = __half22float2(*(__half2*)&p0);
                    float2 f1 = __half22float2(*(__half2*)&p1);
                    Al[kb][h]     = packh(e0 - f0.x, o0 - f0.y);
                    Al[kb][2 + h] = packh(e1 - f1.x, o1 - f1.y);
                }
            }
        }
    }

    // ---- final layer 64->3 in exact fp32 from C fragments
    const float* W6s = (const float*)(smem + OFF_W6);
    const int g   = lane >> 2;
    const int tig = lane & 3;
    float o[2][3];
    #pragma unroll
    for (int s = 0; s < 2; s++) { o[s][0] = 0.f; o[s][1] = 0.f; o[s][2] = 0.f; }

    #pragma unroll
    for (int nb = 0; nb < 8; nb++) {
        const int k0 = nb * 8 + 2 * tig;
        float v0 = C[nb][0], v1 = C[nb][1];       // row g
        float v2 = C[nb][2], v3 = C[nb][3];       // row g + 8
        #pragma unroll
        for (int i = 0; i < 3; i++) {
            float w0 = W6s[i * 64 + k0], w1 = W6s[i * 64 + k0 + 1];
            o[0][i] += v0 * w0 + v1 * w1;
            o[1][i] += v2 * w0 + v3 * w1;
        }
    }
    #pragma unroll
    for (int s = 0; s < 2; s++)
        #pragma unroll
        for (int i = 0; i < 3; i++) {
            o[s][i] += __shfl_xor_sync(0xFFFFFFFFu, o[s][i], 1);
            o[s][i] += __shfl_xor_sync(0xFFFFFFFFu, o[s][i], 2);
        }

    if (tig == 0) {
        #pragma unroll
        for (int s = 0; s < 2; s++) {
            int row = wrb + g + 8 * s;
            int idp = blockIdx.x * CTA_PTS + row;
            if (idp < B) {
                int i3 = idp * 3;
                #pragma unroll
                for (int i = 0; i < 3; i++)
                    gout[i3 + i] = o[s][i] * (galpha[i3 + i] + gbeta[i3 + i]);
            }
        }
    }
}

// ---------------------------------------------------------------------------
extern "C" void kernel_launch(void* const* d_in, const int* in_sizes, int n_in,
                              void* d_out, int out_size) {
    const float* p     = (const float*)d_in[0];
    const float* wi    = (const float*)d_in[1];
    const float* nrm   = (const float*)d_in[2];
    const float* alpha = (const float*)d_in[3];
    const float* beta  = (const float*)d_in[4];
    const float* r     = (const float*)d_in[5];
    const float* W0    = (const float*)d_in[6];
    const float* W1    = (const float*)d_in[7];
    const float* W2    = (const float*)d_in[8];
    const float* W3    = (const float*)d_in[9];
    const float* W4    = (const float*)d_in[10];
    const float* W5    = (const float*)d_in[11];
    const float* W6    = (const float*)d_in[12];

    const int B = in_sizes[0] / 3;

    prep_weights<<<(6 * 4096 + 255) / 256, 256>>>(W0, W1, W2, W3, W4, W5);

    cudaFuncSetAttribute(nrc_mma_kernel,
                         cudaFuncAttributeMaxDynamicSharedMemorySize, SM_TOTAL);
    const int grid = (B + CTA_PTS - 1) / CTA_PTS;
    nrc_mma_kernel<<<grid, NTHREADS, SM_TOTAL>>>(p, wi, nrm, alpha, beta, r, W6,
                                                 (float*)d_out, B);
}

// round 11
// speedup vs baseline: 3.1818x; 1.0544x over previous
#include <cuda_runtime.h>
#include <cuda_fp16.h>
#include <cstdint>

#define NTHREADS 640                // 20 warps, m=16 per warp
#define CTA_PTS  320
#define WSTRIDE  72                 // fp16 elems per weight/staging row (64 + 8 pad)
#define ROWB     (WSTRIDE * 2)      // 144 bytes per row
#define WMAT_B   (64 * ROWB)        // 9216 B per 64x64 fp16 matrix

// ---- SMEM layout (bytes) --------------------------------------------------
#define OFF_W    0                  // 6 fp16 weight matrices = 55296 B
#define OFF_A    (6 * WMAT_B)       // A staging hi [320][72] fp16 = 46080 B
#define A_BYTES  (CTA_PTS * ROWB)
#define OFF_ALO  (OFF_A + A_BYTES)  // A staging lo
#define OFF_W6   (OFF_ALO + A_BYTES)// 192 floats
#define SM_TOTAL (OFF_W6 + 768)     // 148224 B

// ---- Device scratch: fp16 padded weights ----------------------------------
__device__ __align__(16) unsigned char g_Wb[6 * WMAT_B];

__global__ void prep_weights(const float* __restrict__ W0, const float* __restrict__ W1,
                             const float* __restrict__ W2, const float* __restrict__ W3,
                             const float* __restrict__ W4, const float* __restrict__ W5) {
    int i = blockIdx.x * blockDim.x + threadIdx.x;
    if (i >= 6 * 4096) return;
    int l = i >> 12, j = (i >> 6) & 63, k = i & 63;
    const float* W;
    switch (l) {
        case 0: W = W0; break; case 1: W = W1; break; case 2: W = W2; break;
        case 3: W = W3; break; case 4: W = W4; break; default: W = W5; break;
    }
    ((__half*)g_Wb)[(l * 64 + j) * WSTRIDE + k] = __float2half_rn(W[j * 64 + k]);
}

// ---- warp-level MMA helpers (baseline PTX, no sm_103a features) -----------
__device__ __forceinline__ uint32_t smem_u32(const void* p) {
    uint32_t a;
    asm("{ .reg .u64 t; cvta.to.shared.u64 t, %1; cvt.u32.u64 %0, t; }" : "=r"(a) : "l"(p));
    return a;
}
__device__ __forceinline__ void ldsm4(uint32_t& r0, uint32_t& r1, uint32_t& r2, uint32_t& r3,
                                      uint32_t addr) {
    asm volatile("ldmatrix.sync.aligned.m8n8.x4.shared.b16 {%0,%1,%2,%3}, [%4];"
                 : "=r"(r0), "=r"(r1), "=r"(r2), "=r"(r3) : "r"(addr));
}
__device__ __forceinline__ void mma16816(float* c, const uint32_t* a, uint32_t b0, uint32_t b1) {
    asm volatile("mma.sync.aligned.m16n8k16.row.col.f32.f16.f16.f32 "
                 "{%0,%1,%2,%3}, {%4,%5,%6,%7}, {%8,%9}, {%0,%1,%2,%3};"
                 : "+f"(c[0]), "+f"(c[1]), "+f"(c[2]), "+f"(c[3])
                 : "r"(a[0]), "r"(a[1]), "r"(a[2]), "r"(a[3]), "r"(b0), "r"(b1));
}
__device__ __forceinline__ uint32_t packh(float lo, float hi) {
    __half2 t = __floats2half2_rn(lo, hi);              // .x = lower 16 bits
    return *(uint32_t*)&t;
}
__device__ __forceinline__ void put_feat(char* sm, int row, int k, float x) {
    __half h = __float2half_rn(x);
    __half l = __float2half_rn(x - __half2float(h));
    *(__half*)(sm + OFF_A   + row * ROWB + k * 2) = h;
    *(__half*)(sm + OFF_ALO + row * ROWB + k * 2) = l;
}

// ---------------------------------------------------------------------------
// Fully-fused: encode -> 6 layers of 2-pass split-fp16 HMMA (A = Ahi + Alo,
// W single fp16; activations stay in registers, C-frag == next A-frag layout)
// -> exact fp32 final layer. 640 thr = 20 warps (5/SMSP), warp owns m=16.
// Per k-block: 4 ldsm4 W-fragments buffered, then 8 Ahi-MMAs + 8 Alo-MMAs
// (C reuse distance 8). ONE barrier total.
// ---------------------------------------------------------------------------
__global__ __launch_bounds__(NTHREADS, 1)
void nrc_mma_kernel(const float* __restrict__ gp,    const float* __restrict__ gwi,
                    const float* __restrict__ gn,    const float* __restrict__ galpha,
                    const float* __restrict__ gbeta, const float* __restrict__ gr,
                    const float* __restrict__ gW6,   float* __restrict__ gout, int B)
{
    extern __shared__ __align__(16) char smem[];
    const int tid  = threadIdx.x;
    const int lane = tid & 31;
    const int warp = tid >> 5;

    if (tid >= CTA_PTS) {
        // ---- threads 320..639: stage fp16 weights (55296 B = 3456 float4) + W6
        const int t = tid - CTA_PTS;
        const float4* src = (const float4*)g_Wb;
        float4*       dst = (float4*)(smem + OFF_W);
        #pragma unroll
        for (int j = 0; j < 11; j++) {
            int idx = t + j * 320;
            if (idx < 3456) dst[idx] = src[idx];
        }
        if (t < 192) ((float*)(smem + OFF_W6))[t] = gW6[t];
    } else {
        // ---- threads 0..319: encode one point -> staging rows (fp16 hi/lo)
        const int id  = blockIdx.x * CTA_PTS + tid;
        const int idc = (id < B) ? id : (B - 1);
        const int id3 = idc * 3;
        const float PI = 3.14159265358979323846f;
        float pds[3] = {gp[id3], gp[id3 + 1], gp[id3 + 2]};
        #pragma unroll
        for (int d = 0; d < 3; d++) {
            float a = PI * pds[d];
            #pragma unroll
            for (int fq = 0; fq < 6; fq++) {
                float s, c;
                sincosf(a, &s, &c);
                put_feat(smem, tid, d * 12 + fq,     s);
                put_feat(smem, tid, d * 12 + 6 + fq, c);
                a = a + a;                            // exact x2 per octave
            }
        }
        #pragma unroll
        for (int which = 0; which < 2; which++) {
            const float* s3 = which ? gn : gwi;
            const int off = 36 + which * 8;
            float x = s3[id3], y = s3[id3 + 1], z = s3[id3 + 2];
            float nn = sqrtf(x * x + y * y + z * z) + 1e-8f;
            float u  = atan2f(y, x) * 0.15915494309189535f + 0.5f;
            float zn = z / nn;
            zn = fminf(fmaxf(zn, -1.0f + 1e-6f), 1.0f - 1e-6f);
            float v  = acosf(zn) * 0.3183098861837907f;
            #pragma unroll
            for (int i = 0; i < 4; i++) {
                float c  = 0.125f + 0.25f * (float)i;
                float t0 = (u - c) * 4.0f;
                float t1 = (v - c) * 4.0f;
                put_feat(smem, tid, off + i,     expf(-0.5f * t0 * t0));
                put_feat(smem, tid, off + 4 + i, expf(-0.5f * t1 * t1));
            }
        }
        {
            float xr = 1.0f - expf(-gr[idc]);
            #pragma unroll
            for (int i = 0; i < 4; i++) {
                float c = 0.125f + 0.25f * (float)i;
                float t = (xr - c) * 4.0f;
                put_feat(smem, tid, 52 + i, expf(-0.5f * t * t));
            }
        }
        put_feat(smem, tid, 56, galpha[id3]);
        put_feat(smem, tid, 57, galpha[id3 + 1]);
        put_feat(smem, tid, 58, galpha[id3 + 2]);
        put_feat(smem, tid, 59, gbeta[id3]);
        put_feat(smem, tid, 60, gbeta[id3 + 1]);
        put_feat(smem, tid, 61, gbeta[id3 + 2]);
        put_feat(smem, tid, 62, 1.0f);
        put_feat(smem, tid, 63, 1.0f);
    }

    __syncthreads();   // weights + staging visible; everything after is warp-local

    // ---- per-lane ldmatrix address components
    const uint32_t smb  = smem_u32(smem);
    const int rit = lane & 7;
    const uint32_t laneA = ((uint32_t)(rit + ((lane >> 3) & 1) * 8) * ROWB) + ((lane >> 4) & 1) * 16;
    const uint32_t laneB = ((uint32_t)(rit + ((lane >> 4) & 1) * 8) * ROWB) + ((lane >> 3) & 1) * 16;
    const int wrb = warp * 16;                    // warp's first row (point)

    // ---- load layer-0 A fragments (hi + lo) from staging
    uint32_t Ah[4][4], Al[4][4];                  // [k-block][frag reg]
    {
        uint32_t ab = smb + OFF_A + (uint32_t)wrb * ROWB + laneA;
        #pragma unroll
        for (int kb = 0; kb < 4; kb++) {
            uint32_t a = ab + kb * 32;
            ldsm4(Ah[kb][0], Ah[kb][1], Ah[kb][2], Ah[kb][3], a);
            ldsm4(Al[kb][0], Al[kb][1], Al[kb][2], Al[kb][3], a + A_BYTES);
        }
    }

    float C[8][4];                                // [n-block][frag reg]
    #pragma unroll 1
    for (int l = 0; l < 6; l++) {
        #pragma unroll
        for (int nb = 0; nb < 8; nb++)
            #pragma unroll
            for (int i = 0; i < 4; i++) C[nb][i] = 0.0f;

        const uint32_t wmat = smb + OFF_W + (uint32_t)l * WMAT_B + laneB;
        #pragma unroll
        for (int kb = 0; kb < 4; kb++) {
            // buffer all 4 W fragments for this k-block (independent loads)
            uint32_t Wf[4][4];
            #pragma unroll
            for (int np = 0; np < 4; np++)
                ldsm4(Wf[np][0], Wf[np][1], Wf[np][2], Wf[np][3],
                      wmat + (uint32_t)np * (16 * ROWB) + kb * 32);
            // 8 Ahi MMAs, then 8 Alo MMAs: C reuse distance = 8
            #pragma unroll
            for (int np = 0; np < 4; np++) {
                mma16816(C[2 * np],     Ah[kb], Wf[np][0], Wf[np][1]);
                mma16816(C[2 * np + 1], Ah[kb], Wf[np][2], Wf[np][3]);
            }
            #pragma unroll
            for (int np = 0; np < 4; np++) {
                mma16816(C[2 * np],     Al[kb], Wf[np][0], Wf[np][1]);
                mma16816(C[2 * np + 1], Al[kb], Wf[np][2], Wf[np][3]);
            }
        }

        // ReLU
        #pragma unroll
        for (int nb = 0; nb < 8; nb++)
            #pragma unroll
            for (int i = 0; i < 4; i++) C[nb][i] = fmaxf(C[nb][i], 0.0f);

        // register re-split: C-frag (two n8 blocks) == next A-frag (one k16 block)
        if (l < 5) {
            #pragma unroll
            for (int kb = 0; kb < 4; kb++) {
                const float* c0 = C[2 * kb];
                const float* c1 = C[2 * kb + 1];
                #pragma unroll
                for (int h = 0; h < 2; h++) {          // h=0: row g, h=1: row g+8
                    float e0 = c0[2 * h], o0 = c0[2 * h + 1];
                    float e1 = c1[2 * h], o1 = c1[2 * h + 1];
                    uint32_t p0 = packh(e0, o0);
                    uint32_t p1 = packh(e1, o1);
                    Ah[kb][h]     = p0;
                    Ah[kb][2 + h] = p1;
                    float2 f0 = __half22float2(*(__half2*)&p0);
                    float2 f1 = __half22float2(*(__half2*)&p1);
                    Al[kb][h]     = packh(e0 - f0.x, o0 - f0.y);
                    Al[kb][2 + h] = packh(e1 - f1.x, o1 - f1.y);
                }
            }
        }
    }

    // ---- final layer 64->3 in exact fp32 from C fragments
    const float* W6s = (const float*)(smem + OFF_W6);
    const int g   = lane >> 2;
    const int tig = lane & 3;
    float o[2][3];
    #pragma unroll
    for (int s = 0; s < 2; s++) { o[s][0] = 0.f; o[s][1] = 0.f; o[s][2] = 0.f; }

    #pragma unroll
    for (int nb = 0; nb < 8; nb++) {
        const int k0 = nb * 8 + 2 * tig;
        float v0 = C[nb][0], v1 = C[nb][1];       // row g
        float v2 = C[nb][2], v3 = C[nb][3];       // row g + 8
        #pragma unroll
        for (int i = 0; i < 3; i++) {
            float w0 = W6s[i * 64 + k0], w1 = W6s[i * 64 + k0 + 1];
            o[0][i] += v0 * w0 + v1 * w1;
            o[1][i] += v2 * w0 + v3 * w1;
        }
    }
    #pragma unroll
    for (int s = 0; s < 2; s++)
        #pragma unroll
        for (int i = 0; i < 3; i++) {
            o[s][i] += __shfl_xor_sync(0xFFFFFFFFu, o[s][i], 1);
            o[s][i] += __shfl_xor_sync(0xFFFFFFFFu, o[s][i], 2);
        }

    if (tig == 0) {
        #pragma unroll
        for (int s = 0; s < 2; s++) {
            int row = wrb + g + 8 * s;
            int idp = blockIdx.x * CTA_PTS + row;
            if (idp < B) {
                int i3 = idp * 3;
                #pragma unroll
                for (int i = 0; i < 3; i++)
                    gout[i3 + i] = o[s][i] * (galpha[i3 + i] + gbeta[i3 + i]);
            }
        }
    }
}

// ---------------------------------------------------------------------------
extern "C" void kernel_launch(void* const* d_in, const int* in_sizes, int n_in,
                              void* d_out, int out_size) {
    const float* p     = (const float*)d_in[0];
    const float* wi    = (const float*)d_in[1];
    const float* nrm   = (const float*)d_in[2];
    const float* alpha = (const float*)d_in[3];
    const float* beta  = (const float*)d_in[4];
    const float* r     = (const float*)d_in[5];
    const float* W0    = (const float*)d_in[6];
    const float* W1    = (const float*)d_in[7];
    const float* W2    = (const float*)d_in[8];
    const float* W3    = (const float*)d_in[9];
    const float* W4    = (const float*)d_in[10];
    const float* W5    = (const float*)d_in[11];
    const float* W6    = (const float*)d_in[12];

    const int B = in_sizes[0] / 3;

    prep_weights<<<(6 * 4096 + 255) / 256, 256>>>(W0, W1, W2, W3, W4, W5);

    cudaFuncSetAttribute(nrc_mma_kernel,
                         cudaFuncAttributeMaxDynamicSharedMemorySize, SM_TOTAL);
    const int grid = (B + CTA_PTS - 1) / CTA_PTS;
    nrc_mma_kernel<<<grid, NTHREADS, SM_TOTAL>>>(p, wi, nrm, alpha, beta, r, W6,
                                                 (float*)d_out, B);
}

// round 12
// speedup vs baseline: 4.7730x; 1.5001x over previous
#include <cuda_runtime.h>
#include <cuda_fp16.h>
#include <cstdint>

#define NTHREADS 768                // 24 warps, m=16 per warp
#define CTA_PTS  384
#define WSTRIDE  72                 // fp16 elems per weight/staging row (64 + 8 pad)
#define ROWB     (WSTRIDE * 2)      // 144 bytes per row
#define WMAT_B   (64 * ROWB)        // 9216 B per 64x64 fp16 matrix

// ---- SMEM layout (bytes) --------------------------------------------------
#define OFF_W    0                  // 6 fp16 weight matrices = 55296 B
#define OFF_A    (6 * WMAT_B)       // A staging [384][72] fp16 = 55296 B
#define A_BYTES  (CTA_PTS * ROWB)
#define OFF_W6   (OFF_A + A_BYTES)  // 192 floats
#define SM_TOTAL (OFF_W6 + 768)     // 111360 B

// ---- Device scratch: fp16 padded weights ----------------------------------
__device__ __align__(16) unsigned char g_Wb[6 * WMAT_B];

__global__ void prep_weights(const float* __restrict__ W0, const float* __restrict__ W1,
                             const float* __restrict__ W2, const float* __restrict__ W3,
                             const float* __restrict__ W4, const float* __restrict__ W5) {
    int i = blockIdx.x * blockDim.x + threadIdx.x;
    if (i >= 6 * 4096) return;
    int l = i >> 12, j = (i >> 6) & 63, k = i & 63;
    const float* W;
    switch (l) {
        case 0: W = W0; break; case 1: W = W1; break; case 2: W = W2; break;
        case 3: W = W3; break; case 4: W = W4; break; default: W = W5; break;
    }
    ((__half*)g_Wb)[(l * 64 + j) * WSTRIDE + k] = __float2half_rn(W[j * 64 + k]);
}

// ---- warp-level MMA helpers (baseline PTX, no sm_103a features) -----------
__device__ __forceinline__ uint32_t smem_u32(const void* p) {
    uint32_t a;
    asm("{ .reg .u64 t; cvta.to.shared.u64 t, %1; cvt.u32.u64 %0, t; }" : "=r"(a) : "l"(p));
    return a;
}
__device__ __forceinline__ void ldsm4(uint32_t& r0, uint32_t& r1, uint32_t& r2, uint32_t& r3,
                                      uint32_t addr) {
    asm volatile("ldmatrix.sync.aligned.m8n8.x4.shared.b16 {%0,%1,%2,%3}, [%4];"
                 : "=r"(r0), "=r"(r1), "=r"(r2), "=r"(r3) : "r"(addr));
}
__device__ __forceinline__ void mma16816(float* c, const uint32_t* a, uint32_t b0, uint32_t b1) {
    asm volatile("mma.sync.aligned.m16n8k16.row.col.f32.f16.f16.f32 "
                 "{%0,%1,%2,%3}, {%4,%5,%6,%7}, {%8,%9}, {%0,%1,%2,%3};"
                 : "+f"(c[0]), "+f"(c[1]), "+f"(c[2]), "+f"(c[3])
                 : "r"(a[0]), "r"(a[1]), "r"(a[2]), "r"(a[3]), "r"(b0), "r"(b1));
}
__device__ __forceinline__ uint32_t packh(float lo, float hi) {
    __half2 t = __floats2half2_rn(lo, hi);              // .x = lower 16 bits
    return *(uint32_t*)&t;
}
__device__ __forceinline__ void put_feat(char* sm, int row, int k, float x) {
    *(__half*)(sm + OFF_A + row * ROWB + k * 2) = __float2half_rn(x);
}

// ---------------------------------------------------------------------------
// Fully-fused: encode -> 6 layers of single-pass fp16 HMMA (fp32 accumulate;
// activations stay in registers, C-frag == next A-frag layout) -> exact fp32
// final layer. 768 thr = 24 warps (6/SMSP), warp owns m=16 rows.
// Per k-block: 4 W fragments buffered, then 8 MMAs. ONE barrier total.
// ---------------------------------------------------------------------------
__global__ __launch_bounds__(NTHREADS, 1)
void nrc_mma_kernel(const float* __restrict__ gp,    const float* __restrict__ gwi,
                    const float* __restrict__ gn,    const float* __restrict__ galpha,
                    const float* __restrict__ gbeta, const float* __restrict__ gr,
                    const float* __restrict__ gW6,   float* __restrict__ gout, int B)
{
    extern __shared__ __align__(16) char smem[];
    const int tid  = threadIdx.x;
    const int lane = tid & 31;
    const int warp = tid >> 5;

    if (tid >= CTA_PTS) {
        // ---- threads 384..767: stage fp16 weights (55296 B = 3456 float4) + W6
        const int t = tid - CTA_PTS;
        const float4* src = (const float4*)g_Wb;
        float4*       dst = (float4*)(smem + OFF_W);
        #pragma unroll
        for (int j = 0; j < 9; j++) {
            int idx = t + j * 384;
            if (idx < 3456) dst[idx] = src[idx];
        }
        if (t < 192) ((float*)(smem + OFF_W6))[t] = gW6[t];
    } else {
        // ---- threads 0..383: encode one point -> staging row (fp16)
        const int id  = blockIdx.x * CTA_PTS + tid;
        const int idc = (id < B) ? id : (B - 1);
        const int id3 = idc * 3;
        const float PI = 3.14159265358979323846f;
        float pds[3] = {gp[id3], gp[id3 + 1], gp[id3 + 2]};
        #pragma unroll
        for (int d = 0; d < 3; d++) {
            float a = PI * pds[d];
            #pragma unroll
            for (int fq = 0; fq < 6; fq++) {
                float s, c;
                sincosf(a, &s, &c);
                put_feat(smem, tid, d * 12 + fq,     s);
                put_feat(smem, tid, d * 12 + 6 + fq, c);
                a = a + a;                            // exact x2 per octave
            }
        }
        #pragma unroll
        for (int which = 0; which < 2; which++) {
            const float* s3 = which ? gn : gwi;
            const int off = 36 + which * 8;
            float x = s3[id3], y = s3[id3 + 1], z = s3[id3 + 2];
            float nn = sqrtf(x * x + y * y + z * z) + 1e-8f;
            float u  = atan2f(y, x) * 0.15915494309189535f + 0.5f;
            float zn = z / nn;
            zn = fminf(fmaxf(zn, -1.0f + 1e-6f), 1.0f - 1e-6f);
            float v  = acosf(zn) * 0.3183098861837907f;
            #pragma unroll
            for (int i = 0; i < 4; i++) {
                float c  = 0.125f + 0.25f * (float)i;
                float t0 = (u - c) * 4.0f;
                float t1 = (v - c) * 4.0f;
                put_feat(smem, tid, off + i,     expf(-0.5f * t0 * t0));
                put_feat(smem, tid, off + 4 + i, expf(-0.5f * t1 * t1));
            }
        }
        {
            float xr = 1.0f - expf(-gr[idc]);
            #pragma unroll
            for (int i = 0; i < 4; i++) {
                float c = 0.125f + 0.25f * (float)i;
                float t = (xr - c) * 4.0f;
                put_feat(smem, tid, 52 + i, expf(-0.5f * t * t));
            }
        }
        put_feat(smem, tid, 56, galpha[id3]);
        put_feat(smem, tid, 57, galpha[id3 + 1]);
        put_feat(smem, tid, 58, galpha[id3 + 2]);
        put_feat(smem, tid, 59, gbeta[id3]);
        put_feat(smem, tid, 60, gbeta[id3 + 1]);
        put_feat(smem, tid, 61, gbeta[id3 + 2]);
        put_feat(smem, tid, 62, 1.0f);
        put_feat(smem, tid, 63, 1.0f);
    }

    __syncthreads();   // weights + staging visible; everything after is warp-local

    // ---- per-lane ldmatrix address components
    const uint32_t smb  = smem_u32(smem);
    const int rit = lane & 7;
    const uint32_t laneA = ((uint32_t)(rit + ((lane >> 3) & 1) * 8) * ROWB) + ((lane >> 4) & 1) * 16;
    const uint32_t laneB = ((uint32_t)(rit + ((lane >> 4) & 1) * 8) * ROWB) + ((lane >> 3) & 1) * 16;
    const int wrb = warp * 16;                    // warp's first row (point)

    // ---- load layer-0 A fragments from staging
    uint32_t Ah[4][4];                            // [k-block][frag reg]
    {
        uint32_t ab = smb + OFF_A + (uint32_t)wrb * ROWB + laneA;
        #pragma unroll
        for (int kb = 0; kb < 4; kb++)
            ldsm4(Ah[kb][0], Ah[kb][1], Ah[kb][2], Ah[kb][3], ab + kb * 32);
    }

    float C[8][4];                                // [n-block][frag reg]
    #pragma unroll 1
    for (int l = 0; l < 6; l++) {
        #pragma unroll
        for (int nb = 0; nb < 8; nb++)
            #pragma unroll
            for (int i = 0; i < 4; i++) C[nb][i] = 0.0f;

        const uint32_t wmat = smb + OFF_W + (uint32_t)l * WMAT_B + laneB;
        #pragma unroll
        for (int kb = 0; kb < 4; kb++) {
            // buffer all 4 W fragments for this k-block (independent loads)
            uint32_t Wf[4][4];
            #pragma unroll
            for (int np = 0; np < 4; np++)
                ldsm4(Wf[np][0], Wf[np][1], Wf[np][2], Wf[np][3],
                      wmat + (uint32_t)np * (16 * ROWB) + kb * 32);
            #pragma unroll
            for (int np = 0; np < 4; np++) {
                mma16816(C[2 * np],     Ah[kb], Wf[np][0], Wf[np][1]);
                mma16816(C[2 * np + 1], Ah[kb], Wf[np][2], Wf[np][3]);
            }
        }

        // ReLU + register re-split: C-frag (two n8 blocks) == next A-frag
        #pragma unroll
        for (int nb = 0; nb < 8; nb++)
            #pragma unroll
            for (int i = 0; i < 4; i++) C[nb][i] = fmaxf(C[nb][i], 0.0f);

        if (l < 5) {
            #pragma unroll
            for (int kb = 0; kb < 4; kb++) {
                const float* c0 = C[2 * kb];
                const float* c1 = C[2 * kb + 1];
                #pragma unroll
                for (int h = 0; h < 2; h++) {          // h=0: row g, h=1: row g+8
                    Ah[kb][h]     = packh(c0[2 * h], c0[2 * h + 1]);
                    Ah[kb][2 + h] = packh(c1[2 * h], c1[2 * h + 1]);
                }
            }
        }
    }

    // ---- final layer 64->3 in exact fp32 from C fragments
    const float* W6s = (const float*)(smem + OFF_W6);
    const int g   = lane >> 2;
    const int tig = lane & 3;
    float o[2][3];
    #pragma unroll
    for (int s = 0; s < 2; s++) { o[s][0] = 0.f; o[s][1] = 0.f; o[s][2] = 0.f; }

    #pragma unroll
    for (int nb = 0; nb < 8; nb++) {
        const int k0 = nb * 8 + 2 * tig;
        float v0 = C[nb][0], v1 = C[nb][1];       // row g
        float v2 = C[nb][2], v3 = C[nb][3];       // row g + 8
        #pragma unroll
        for (int i = 0; i < 3; i++) {
            float w0 = W6s[i * 64 + k0], w1 = W6s[i * 64 + k0 + 1];
            o[0][i] += v0 * w0 + v1 * w1;
            o[1][i] += v2 * w0 + v3 * w1;
        }
    }
    #pragma unroll
    for (int s = 0; s < 2; s++)
        #pragma unroll
        for (int i = 0; i < 3; i++) {
            o[s][i] += __shfl_xor_sync(0xFFFFFFFFu, o[s][i], 1);
            o[s][i] += __shfl_xor_sync(0xFFFFFFFFu, o[s][i], 2);
        }

    if (tig == 0) {
        #pragma unroll
        for (int s = 0; s < 2; s++) {
            int row = wrb + g + 8 * s;
            int idp = blockIdx.x * CTA_PTS + row;
            if (idp < B) {
                int i3 = idp * 3;
                #pragma unroll
                for (int i = 0; i < 3; i++)
                    gout[i3 + i] = o[s][i] * (galpha[i3 + i] + gbeta[i3 + i]);
            }
        }
    }
}

// ---------------------------------------------------------------------------
extern "C" void kernel_launch(void* const* d_in, const int* in_sizes, int n_in,
                              void* d_out, int out_size) {
    const float* p     = (const float*)d_in[0];
    const float* wi    = (const float*)d_in[1];
    const float* nrm   = (const float*)d_in[2];
    const float* alpha = (const float*)d_in[3];
    const float* beta  = (const float*)d_in[4];
    const float* r     = (const float*)d_in[5];
    const float* W0    = (const float*)d_in[6];
    const float* W1    = (const float*)d_in[7];
    const float* W2    = (const float*)d_in[8];
    const float* W3    = (const float*)d_in[9];
    const float* W4    = (const float*)d_in[10];
    const float* W5    = (const float*)d_in[11];
    const float* W6    = (const float*)d_in[12];

    const int B = in_sizes[0] / 3;

    prep_weights<<<(6 * 4096 + 255) / 256, 256>>>(W0, W1, W2, W3, W4, W5);

    cudaFuncSetAttribute(nrc_mma_kernel,
                         cudaFuncAttributeMaxDynamicSharedMemorySize, SM_TOTAL);
    const int grid = (B + CTA_PTS - 1) / CTA_PTS;
    nrc_mma_kernel<<<grid, NTHREADS, SM_TOTAL>>>(p, wi, nrm, alpha, beta, r, W6,
                                                 (float*)d_out, B);
}

// round 13
// speedup vs baseline: 5.3416x; 1.1191x over previous
#include <cuda_runtime.h>
#include <cuda_fp16.h>
#include <cstdint>

#define NTHREADS 512                // 16 warps, m=32 per warp
#define CTA_PTS  512
#define WSTRIDE  72                 // fp16 elems per weight/staging row (64 + 8 pad)
#define ROWB     (WSTRIDE * 2)      // 144 bytes per row
#define WMAT_B   (64 * ROWB)        // 9216 B per 64x64 fp16 matrix

// ---- SMEM layout (bytes) --------------------------------------------------
#define OFF_W    0                  // 6 fp16 weight matrices = 55296 B
#define OFF_A    (6 * WMAT_B)       // A staging [512][72] fp16 = 73728 B
#define A_BYTES  (CTA_PTS * ROWB)
#define OFF_W6   (OFF_A + A_BYTES)  // 192 floats
#define SM_TOTAL (OFF_W6 + 768)     // 129792 B

// ---- Device scratch: fp16 padded weights ----------------------------------
__device__ __align__(16) unsigned char g_Wb[6 * WMAT_B];

__global__ void prep_weights(const float* __restrict__ W0, const float* __restrict__ W1,
                             const float* __restrict__ W2, const float* __restrict__ W3,
                             const float* __restrict__ W4, const float* __restrict__ W5) {
    int i = blockIdx.x * blockDim.x + threadIdx.x;
    if (i >= 6 * 4096) return;
    int l = i >> 12, j = (i >> 6) & 63, k = i & 63;
    const float* W;
    switch (l) {
        case 0: W = W0; break; case 1: W = W1; break; case 2: W = W2; break;
        case 3: W = W3; break; case 4: W = W4; break; default: W = W5; break;
    }
    ((__half*)g_Wb)[(l * 64 + j) * WSTRIDE + k] = __float2half_rn(W[j * 64 + k]);
}

// ---- warp-level MMA helpers (baseline PTX, no sm_103a features) -----------
__device__ __forceinline__ uint32_t smem_u32(const void* p) {
    uint32_t a;
    asm("{ .reg .u64 t; cvta.to.shared.u64 t, %1; cvt.u32.u64 %0, t; }" : "=r"(a) : "l"(p));
    return a;
}
__device__ __forceinline__ void ldsm4(uint32_t& r0, uint32_t& r1, uint32_t& r2, uint32_t& r3,
                                      uint32_t addr) {
    asm volatile("ldmatrix.sync.aligned.m8n8.x4.shared.b16 {%0,%1,%2,%3}, [%4];"
                 : "=r"(r0), "=r"(r1), "=r"(r2), "=r"(r3) : "r"(addr));
}
__device__ __forceinline__ void mma16816(float* c, const uint32_t* a, uint32_t b0, uint32_t b1) {
    asm volatile("mma.sync.aligned.m16n8k16.row.col.f32.f16.f16.f32 "
                 "{%0,%1,%2,%3}, {%4,%5,%6,%7}, {%8,%9}, {%0,%1,%2,%3};"
                 : "+f"(c[0]), "+f"(c[1]), "+f"(c[2]), "+f"(c[3])
                 : "r"(a[0]), "r"(a[1]), "r"(a[2]), "r"(a[3]), "r"(b0), "r"(b1));
}
__device__ __forceinline__ uint32_t packh(float lo, float hi) {
    __half2 t = __floats2half2_rn(lo, hi);              // .x = lower 16 bits
    return *(uint32_t*)&t;
}
__device__ __forceinline__ void put_feat(char* sm, int row, int k, float x) {
    *(__half*)(sm + OFF_A + row * ROWB + k * 2) = __float2half_rn(x);
}

// ---------------------------------------------------------------------------
// Fully-fused: encode -> 6 layers of single-pass fp16 HMMA (fp32 accumulate;
// activations stay in registers, C-frag == next A-frag layout) -> exact fp32
// final layer. 512 thr = 16 warps, warp owns m=32 rows (2 m16 tiles) so each
// W fragment load feeds FOUR MMAs (halves LDSM traffic per point vs m=16).
// ONE barrier total.
// ---------------------------------------------------------------------------
__global__ __launch_bounds__(NTHREADS, 1)
void nrc_mma_kernel(const float* __restrict__ gp,    const float* __restrict__ gwi,
                    const float* __restrict__ gn,    const float* __restrict__ galpha,
                    const float* __restrict__ gbeta, const float* __restrict__ gr,
                    const float* __restrict__ gW6,   float* __restrict__ gout, int B)
{
    extern __shared__ __align__(16) char smem[];
    const int tid  = threadIdx.x;
    const int lane = tid & 31;
    const int warp = tid >> 5;

    // ---- every thread: stage a slice of weights, then encode its point
    {
        const float4* src = (const float4*)g_Wb;
        float4*       dst = (float4*)(smem + OFF_W);
        #pragma unroll
        for (int j = 0; j < 7; j++) {
            int idx = tid + j * NTHREADS;
            if (idx < 3456) dst[idx] = src[idx];
        }
        if (tid < 192) ((float*)(smem + OFF_W6))[tid] = gW6[tid];
    }
    {
        const int id  = blockIdx.x * CTA_PTS + tid;
        const int idc = (id < B) ? id : (B - 1);
        const int id3 = idc * 3;
        const float PI = 3.14159265358979323846f;
        float pds[3] = {gp[id3], gp[id3 + 1], gp[id3 + 2]};
        #pragma unroll
        for (int d = 0; d < 3; d++) {
            float a = PI * pds[d];
            #pragma unroll
            for (int fq = 0; fq < 6; fq++) {
                float s, c;
                sincosf(a, &s, &c);
                put_feat(smem, tid, d * 12 + fq,     s);
                put_feat(smem, tid, d * 12 + 6 + fq, c);
                a = a + a;                            // exact x2 per octave
            }
        }
        #pragma unroll
        for (int which = 0; which < 2; which++) {
            const float* s3 = which ? gn : gwi;
            const int off = 36 + which * 8;
            float x = s3[id3], y = s3[id3 + 1], z = s3[id3 + 2];
            float nn = sqrtf(x * x + y * y + z * z) + 1e-8f;
            float u  = atan2f(y, x) * 0.15915494309189535f + 0.5f;
            float zn = z / nn;
            zn = fminf(fmaxf(zn, -1.0f + 1e-6f), 1.0f - 1e-6f);
            float v  = acosf(zn) * 0.3183098861837907f;
            #pragma unroll
            for (int i = 0; i < 4; i++) {
                float c  = 0.125f + 0.25f * (float)i;
                float t0 = (u - c) * 4.0f;
                float t1 = (v - c) * 4.0f;
                put_feat(smem, tid, off + i,     expf(-0.5f * t0 * t0));
                put_feat(smem, tid, off + 4 + i, expf(-0.5f * t1 * t1));
            }
        }
        {
            float xr = 1.0f - expf(-gr[idc]);
            #pragma unroll
            for (int i = 0; i < 4; i++) {
                float c = 0.125f + 0.25f * (float)i;
                float t = (xr - c) * 4.0f;
                put_feat(smem, tid, 52 + i, expf(-0.5f * t * t));
            }
        }
        put_feat(smem, tid, 56, galpha[id3]);
        put_feat(smem, tid, 57, galpha[id3 + 1]);
        put_feat(smem, tid, 58, galpha[id3 + 2]);
        put_feat(smem, tid, 59, gbeta[id3]);
        put_feat(smem, tid, 60, gbeta[id3 + 1]);
        put_feat(smem, tid, 61, gbeta[id3 + 2]);
        put_feat(smem, tid, 62, 1.0f);
        put_feat(smem, tid, 63, 1.0f);
    }

    __syncthreads();   // weights + staging visible; everything after is warp-local

    // ---- per-lane ldmatrix address components
    const uint32_t smb  = smem_u32(smem);
    const int rit = lane & 7;
    const uint32_t laneA = ((uint32_t)(rit + ((lane >> 3) & 1) * 8) * ROWB) + ((lane >> 4) & 1) * 16;
    const uint32_t laneB = ((uint32_t)(rit + ((lane >> 4) & 1) * 8) * ROWB) + ((lane >> 3) & 1) * 16;
    const int wrb = warp * 32;                    // warp's first row (point)

    // ---- load layer-0 A fragments from staging (2 m16 tiles per k-block)
    uint32_t Ah[4][8];                            // [k-block][mt*4 + reg]
    {
        uint32_t ab = smb + OFF_A + (uint32_t)wrb * ROWB + laneA;
        #pragma unroll
        for (int kb = 0; kb < 4; kb++)
            #pragma unroll
            for (int mt = 0; mt < 2; mt++)
                ldsm4(Ah[kb][4 * mt], Ah[kb][4 * mt + 1],
                      Ah[kb][4 * mt + 2], Ah[kb][4 * mt + 3],
                      ab + mt * 16 * ROWB + kb * 32);
    }

    float C[8][8];                                // [n-block][mt*4 + reg]
    #pragma unroll 1
    for (int l = 0; l < 6; l++) {
        #pragma unroll
        for (int nb = 0; nb < 8; nb++)
            #pragma unroll
            for (int i = 0; i < 8; i++) C[nb][i] = 0.0f;

        const uint32_t wmat = smb + OFF_W + (uint32_t)l * WMAT_B + laneB;
        #pragma unroll
        for (int kb = 0; kb < 4; kb++) {
            // buffer all 4 W fragments for this k-block (independent loads)
            uint32_t Wf[4][4];
            #pragma unroll
            for (int np = 0; np < 4; np++)
                ldsm4(Wf[np][0], Wf[np][1], Wf[np][2], Wf[np][3],
                      wmat + (uint32_t)np * (16 * ROWB) + kb * 32);
            // each fragment feeds 4 MMAs (2 n8 blocks x 2 m16 tiles)
            #pragma unroll
            for (int np = 0; np < 4; np++)
                #pragma unroll
                for (int mt = 0; mt < 2; mt++) {
                    mma16816(&C[2 * np][4 * mt],     &Ah[kb][4 * mt], Wf[np][0], Wf[np][1]);
                    mma16816(&C[2 * np + 1][4 * mt], &Ah[kb][4 * mt], Wf[np][2], Wf[np][3]);
                }
        }

        // ReLU + register re-split: C-frag (two n8 blocks) == next A-frag
        #pragma unroll
        for (int nb = 0; nb < 8; nb++)
            #pragma unroll
            for (int i = 0; i < 8; i++) C[nb][i] = fmaxf(C[nb][i], 0.0f);

        if (l < 5) {
            #pragma unroll
            for (int kb = 0; kb < 4; kb++)
                #pragma unroll
                for (int mt = 0; mt < 2; mt++) {
                    const float* c0 = &C[2 * kb][4 * mt];
                    const float* c1 = &C[2 * kb + 1][4 * mt];
                    #pragma unroll
                    for (int h = 0; h < 2; h++) {      // h=0: row g, h=1: row g+8
                        Ah[kb][4 * mt + h]     = packh(c0[2 * h], c0[2 * h + 1]);
                        Ah[kb][4 * mt + 2 + h] = packh(c1[2 * h], c1[2 * h + 1]);
                    }
                }
        }
    }

    // ---- final layer 64->3 in exact fp32 from C fragments
    const float* W6s = (const float*)(smem + OFF_W6);
    const int g   = lane >> 2;
    const int tig = lane & 3;
    float o[4][3];
    #pragma unroll
    for (int s = 0; s < 4; s++) { o[s][0] = 0.f; o[s][1] = 0.f; o[s][2] = 0.f; }

    #pragma unroll
    for (int nb = 0; nb < 8; nb++) {
        const int k0 = nb * 8 + 2 * tig;
        #pragma unroll
        for (int mt = 0; mt < 2; mt++) {
            float v0 = C[nb][4 * mt + 0], v1 = C[nb][4 * mt + 1];   // row g + 16mt
            float v2 = C[nb][4 * mt + 2], v3 = C[nb][4 * mt + 3];   // row g + 16mt + 8
            #pragma unroll
            for (int i = 0; i < 3; i++) {
                float w0 = W6s[i * 64 + k0], w1 = W6s[i * 64 + k0 + 1];
                o[2 * mt][i]     += v0 * w0 + v1 * w1;
                o[2 * mt + 1][i] += v2 * w0 + v3 * w1;
            }
        }
    }
    #pragma unroll
    for (int s = 0; s < 4; s++)
        #pragma unroll
        for (int i = 0; i < 3; i++) {
            o[s][i] += __shfl_xor_sync(0xFFFFFFFFu, o[s][i], 1);
            o[s][i] += __shfl_xor_sync(0xFFFFFFFFu, o[s][i], 2);
        }

    if (tig == 0) {
        #pragma unroll
        for (int s = 0; s < 4; s++) {
            int row = wrb + g + 16 * (s >> 1) + 8 * (s & 1);
            int idp = blockIdx.x * CTA_PTS + row;
            if (idp < B) {
                int i3 = idp * 3;
                #pragma unroll
                for (int i = 0; i < 3; i++)
                    gout[i3 + i] = o[s][i] * (galpha[i3 + i] + gbeta[i3 + i]);
            }
        }
    }
}

// ---------------------------------------------------------------------------
extern "C" void kernel_launch(void* const* d_in, const int* in_sizes, int n_in,
                              void* d_out, int out_size) {
    const float* p     = (const float*)d_in[0];
    const float* wi    = (const float*)d_in[1];
    const float* nrm   = (const float*)d_in[2];
    const float* alpha = (const float*)d_in[3];
    const float* beta  = (const float*)d_in[4];
    const float* r     = (const float*)d_in[5];
    const float* W0    = (const float*)d_in[6];
    const float* W1    = (const float*)d_in[7];
    const float* W2    = (const float*)d_in[8];
    const float* W3    = (const float*)d_in[9];
    const float* W4    = (const float*)d_in[10];
    const float* W5    = (const float*)d_in[11];
    const float* W6    = (const float*)d_in[12];

    const int B = in_sizes[0] / 3;

    prep_weights<<<(6 * 4096 + 255) / 256, 256>>>(W0, W1, W2, W3, W4, W5);

    cudaFuncSetAttribute(nrc_mma_kernel,
                         cudaFuncAttributeMaxDynamicSharedMemorySize, SM_TOTAL);
    const int grid = (B + CTA_PTS - 1) / CTA_PTS;
    nrc_mma_kernel<<<grid, NTHREADS, SM_TOTAL>>>(p, wi, nrm, alpha, beta, r, W6,
                                                 (float*)d_out, B);
}

// round 14
// speedup vs baseline: 6.2736x; 1.1745x over previous
#include <cuda_runtime.h>
#include <cuda_fp16.h>
#include <cstdint>

#define NTHREADS 512                // 16 warps, m=32 per warp
#define CTA_PTS  512
#define WSTRIDE  72                 // fp16 elems per weight/staging row (64 + 8 pad)
#define ROWB     (WSTRIDE * 2)      // 144 bytes per row
#define WMAT_B   (64 * ROWB)        // 9216 B per 64x64 fp16 matrix

// ---- SMEM layout (bytes) --------------------------------------------------
#define OFF_W    0                  // 6 fp16 weight matrices = 55296 B
#define OFF_A    (6 * WMAT_B)       // A staging [512][72] fp16 = 73728 B
#define A_BYTES  (CTA_PTS * ROWB)
#define OFF_W6   (OFF_A + A_BYTES)  // 192 floats
#define SM_TOTAL (OFF_W6 + 768)     // 129792 B

// ---- Device scratch: fp16 padded weights ----------------------------------
__device__ __align__(16) unsigned char g_Wb[6 * WMAT_B];

__global__ void prep_weights(const float* __restrict__ W0, const float* __restrict__ W1,
                             const float* __restrict__ W2, const float* __restrict__ W3,
                             const float* __restrict__ W4, const float* __restrict__ W5) {
    int i = blockIdx.x * blockDim.x + threadIdx.x;
    if (i >= 6 * 4096) return;
    int l = i >> 12, j = (i >> 6) & 63, k = i & 63;
    const float* W;
    switch (l) {
        case 0: W = W0; break; case 1: W = W1; break; case 2: W = W2; break;
        case 3: W = W3; break; case 4: W = W4; break; default: W = W5; break;
    }
    ((__half*)g_Wb)[(l * 64 + j) * WSTRIDE + k] = __float2half_rn(W[j * 64 + k]);
}

// ---- warp-level MMA helpers (baseline PTX, no sm_103a features) -----------
__device__ __forceinline__ uint32_t smem_u32(const void* p) {
    uint32_t a;
    asm("{ .reg .u64 t; cvta.to.shared.u64 t, %1; cvt.u32.u64 %0, t; }" : "=r"(a) : "l"(p));
    return a;
}
__device__ __forceinline__ void ldsm4(uint32_t& r0, uint32_t& r1, uint32_t& r2, uint32_t& r3,
                                      uint32_t addr) {
    asm volatile("ldmatrix.sync.aligned.m8n8.x4.shared.b16 {%0,%1,%2,%3}, [%4];"
                 : "=r"(r0), "=r"(r1), "=r"(r2), "=r"(r3) : "r"(addr));
}
__device__ __forceinline__ void mma16816(float* c, const uint32_t* a, uint32_t b0, uint32_t b1) {
    asm volatile("mma.sync.aligned.m16n8k16.row.col.f32.f16.f16.f32 "
                 "{%0,%1,%2,%3}, {%4,%5,%6,%7}, {%8,%9}, {%0,%1,%2,%3};"
                 : "+f"(c[0]), "+f"(c[1]), "+f"(c[2]), "+f"(c[3])
                 : "r"(a[0]), "r"(a[1]), "r"(a[2]), "r"(a[3]), "r"(b0), "r"(b1));
}
__device__ __forceinline__ uint32_t packh(float lo, float hi) {
    __half2 t = __floats2half2_rn(lo, hi);              // .x = lower 16 bits
    return *(uint32_t*)&t;
}

// ---------------------------------------------------------------------------
// Fully-fused: low-instruction encode (3 sincosf + double-angle octaves,
// __expf one-blobs, 8x STS.128 staging) -> 6 fully-unrolled single-pass fp16
// HMMA layers (fp32 accumulate; activations register-resident, C-frag == next
// A-frag layout) -> exact fp32 final layer. 512 thr = 16 warps, m=32/warp:
// each W fragment feeds FOUR MMAs. ONE barrier total.
// ---------------------------------------------------------------------------
__global__ __launch_bounds__(NTHREADS, 1)
void nrc_mma_kernel(const float* __restrict__ gp,    const float* __restrict__ gwi,
                    const float* __restrict__ gn,    const float* __restrict__ galpha,
                    const float* __restrict__ gbeta, const float* __restrict__ gr,
                    const float* __restrict__ gW6,   float* __restrict__ gout, int B)
{
    extern __shared__ __align__(16) char smem[];
    const int tid  = threadIdx.x;
    const int lane = tid & 31;
    const int warp = tid >> 5;

    // ---- stage weights (55296 B = 3456 float4) + W6
    {
        const float4* src = (const float4*)g_Wb;
        float4*       dst = (float4*)(smem + OFF_W);
        #pragma unroll
        for (int j = 0; j < 7; j++) {
            int idx = tid + j * NTHREADS;
            if (idx < 3456) dst[idx] = src[idx];
        }
        if (tid < 192) ((float*)(smem + OFF_W6))[tid] = gW6[tid];
    }

    // ---- encode one point -> f[64] in registers
    {
        const int id  = blockIdx.x * CTA_PTS + tid;
        const int idc = (id < B) ? id : (B - 1);
        const int id3 = idc * 3;
        const float PI = 3.14159265358979323846f;
        float f[64];

        // frequency embedding: 1 sincosf per dim + exact double-angle octaves
        #pragma unroll
        for (int d = 0; d < 3; d++) {
            float a = PI * gp[id3 + d];
            float s, c;
            sincosf(a, &s, &c);
            f[d * 12 + 0] = s;
            f[d * 12 + 6] = c;
            #pragma unroll
            for (int fq = 1; fq < 6; fq++) {
                float s2 = 2.0f * s * c;
                float c2 = c * c - s * s;
                s = s2; c = c2;
                f[d * 12 + fq]     = s;
                f[d * 12 + 6 + fq] = c;
            }
        }
        // spherical one-blob for wi and n
        #pragma unroll
        for (int which = 0; which < 2; which++) {
            const float* s3 = which ? gn : gwi;
            const int off = 36 + which * 8;
            float x = s3[id3], y = s3[id3 + 1], z = s3[id3 + 2];
            float nn = sqrtf(x * x + y * y + z * z) + 1e-8f;
            float u  = atan2f(y, x) * 0.15915494309189535f + 0.5f;
            float zn = z / nn;
            zn = fminf(fmaxf(zn, -1.0f + 1e-6f), 1.0f - 1e-6f);
            float v  = acosf(zn) * 0.3183098861837907f;
            #pragma unroll
            for (int i = 0; i < 4; i++) {
                float c  = 0.125f + 0.25f * (float)i;
                float t0 = (u - c) * 4.0f;
                float t1 = (v - c) * 4.0f;
                f[off + i]     = __expf(-0.5f * t0 * t0);
                f[off + 4 + i] = __expf(-0.5f * t1 * t1);
            }
        }
        // roughness one-blob
        {
            float xr = 1.0f - __expf(-gr[idc]);
            #pragma unroll
            for (int i = 0; i < 4; i++) {
                float c = 0.125f + 0.25f * (float)i;
                float t = (xr - c) * 4.0f;
                f[52 + i] = __expf(-0.5f * t * t);
            }
        }
        f[56] = galpha[id3]; f[57] = galpha[id3 + 1]; f[58] = galpha[id3 + 2];
        f[59] = gbeta[id3];  f[60] = gbeta[id3 + 1];  f[61] = gbeta[id3 + 2];
        f[62] = 1.0f; f[63] = 1.0f;

        // pack + batched STS.128 (row stride 144B -> conflict-free per phase)
        char* base = smem + OFF_A + tid * ROWB;
        #pragma unroll
        for (int ch = 0; ch < 8; ch++) {
            uint4 v;
            v.x = packh(f[ch * 8 + 0], f[ch * 8 + 1]);
            v.y = packh(f[ch * 8 + 2], f[ch * 8 + 3]);
            v.z = packh(f[ch * 8 + 4], f[ch * 8 + 5]);
            v.w = packh(f[ch * 8 + 6], f[ch * 8 + 7]);
            *(uint4*)(base + ch * 16) = v;
        }
    }

    __syncthreads();   // weights + staging visible; everything after is warp-local

    // ---- per-lane ldmatrix address components
    const uint32_t smb  = smem_u32(smem);
    const int rit = lane & 7;
    const uint32_t laneA = ((uint32_t)(rit + ((lane >> 3) & 1) * 8) * ROWB) + ((lane >> 4) & 1) * 16;
    const uint32_t laneB = ((uint32_t)(rit + ((lane >> 4) & 1) * 8) * ROWB) + ((lane >> 3) & 1) * 16;
    const int wrb = warp * 32;                    // warp's first row (point)

    // ---- load layer-0 A fragments from staging (2 m16 tiles per k-block)
    uint32_t Ah[4][8];                            // [k-block][mt*4 + reg]
    {
        uint32_t ab = smb + OFF_A + (uint32_t)wrb * ROWB + laneA;
        #pragma unroll
        for (int kb = 0; kb < 4; kb++)
            #pragma unroll
            for (int mt = 0; mt < 2; mt++)
                ldsm4(Ah[kb][4 * mt], Ah[kb][4 * mt + 1],
                      Ah[kb][4 * mt + 2], Ah[kb][4 * mt + 3],
                      ab + mt * 16 * ROWB + kb * 32);
    }

    float C[8][8];                                // [n-block][mt*4 + reg]
    #pragma unroll
    for (int l = 0; l < 6; l++) {
        #pragma unroll
        for (int nb = 0; nb < 8; nb++)
            #pragma unroll
            for (int i = 0; i < 8; i++) C[nb][i] = 0.0f;

        const uint32_t wmat = smb + OFF_W + (uint32_t)l * WMAT_B + laneB;
        #pragma unroll
        for (int kb = 0; kb < 4; kb++) {
            // buffer all 4 W fragments for this k-block (independent loads)
            uint32_t Wf[4][4];
            #pragma unroll
            for (int np = 0; np < 4; np++)
                ldsm4(Wf[np][0], Wf[np][1], Wf[np][2], Wf[np][3],
                      wmat + (uint32_t)np * (16 * ROWB) + kb * 32);
            // each fragment feeds 4 MMAs (2 n8 blocks x 2 m16 tiles)
            #pragma unroll
            for (int np = 0; np < 4; np++)
                #pragma unroll
                for (int mt = 0; mt < 2; mt++) {
                    mma16816(&C[2 * np][4 * mt],     &Ah[kb][4 * mt], Wf[np][0], Wf[np][1]);
                    mma16816(&C[2 * np + 1][4 * mt], &Ah[kb][4 * mt], Wf[np][2], Wf[np][3]);
                }
        }

        // ReLU + register re-split: C-frag (two n8 blocks) == next A-frag
        #pragma unroll
        for (int nb = 0; nb < 8; nb++)
            #pragma unroll
            for (int i = 0; i < 8; i++) C[nb][i] = fmaxf(C[nb][i], 0.0f);

        if (l < 5) {
            #pragma unroll
            for (int kb = 0; kb < 4; kb++)
                #pragma unroll
                for (int mt = 0; mt < 2; mt++) {
                    const float* c0 = &C[2 * kb][4 * mt];
                    const float* c1 = &C[2 * kb + 1][4 * mt];
                    #pragma unroll
                    for (int h = 0; h < 2; h++) {      // h=0: row g, h=1: row g+8
                        Ah[kb][4 * mt + h]     = packh(c0[2 * h], c0[2 * h + 1]);
                        Ah[kb][4 * mt + 2 + h] = packh(c1[2 * h], c1[2 * h + 1]);
                    }
                }
        }
    }

    // ---- final layer 64->3 in exact fp32 from C fragments
    const float* W6s = (const float*)(smem + OFF_W6);
    const int g   = lane >> 2;
    const int tig = lane & 3;
    float o[4][3];
    #pragma unroll
    for (int s = 0; s < 4; s++) { o[s][0] = 0.f; o[s][1] = 0.f; o[s][2] = 0.f; }

    #pragma unroll
    for (int nb = 0; nb < 8; nb++) {
        const int k0 = nb * 8 + 2 * tig;
        #pragma unroll
        for (int mt = 0; mt < 2; mt++) {
            float v0 = C[nb][4 * mt + 0], v1 = C[nb][4 * mt + 1];   // row g + 16mt
            float v2 = C[nb][4 * mt + 2], v3 = C[nb][4 * mt + 3];   // row g + 16mt + 8
            #pragma unroll
            for (int i = 0; i < 3; i++) {
                float w0 = W6s[i * 64 + k0], w1 = W6s[i * 64 + k0 + 1];
                o[2 * mt][i]     += v0 * w0 + v1 * w1;
                o[2 * mt + 1][i] += v2 * w0 + v3 * w1;
            }
        }
    }
    #pragma unroll
    for (int s = 0; s < 4; s++)
        #pragma unroll
        for (int i = 0; i < 3; i++) {
            o[s][i] += __shfl_xor_sync(0xFFFFFFFFu, o[s][i], 1);
            o[s][i] += __shfl_xor_sync(0xFFFFFFFFu, o[s][i], 2);
        }

    if (tig == 0) {
        #pragma unroll
        for (int s = 0; s < 4; s++) {
            int row = wrb + g + 16 * (s >> 1) + 8 * (s & 1);
            int idp = blockIdx.x * CTA_PTS + row;
            if (idp < B) {
                int i3 = idp * 3;
                #pragma unroll
                for (int i = 0; i < 3; i++)
                    gout[i3 + i] = o[s][i] * (galpha[i3 + i] + gbeta[i3 + i]);
            }
        }
    }
}

// ---------------------------------------------------------------------------
extern "C" void kernel_launch(void* const* d_in, const int* in_sizes, int n_in,
                              void* d_out, int out_size) {
    const float* p     = (const float*)d_in[0];
    const float* wi    = (const float*)d_in[1];
    const float* nrm   = (const float*)d_in[2];
    const float* alpha = (const float*)d_in[3];
    const float* beta  = (const float*)d_in[4];
    const float* r     = (const float*)d_in[5];
    const float* W0    = (const float*)d_in[6];
    const float* W1    = (const float*)d_in[7];
    const float* W2    = (const float*)d_in[8];
    const float* W3    = (const float*)d_in[9];
    const float* W4    = (const float*)d_in[10];
    const float* W5    = (const float*)d_in[11];
    const float* W6    = (const float*)d_in[12];

    const int B = in_sizes[0] / 3;

    prep_weights<<<(6 * 4096 + 255) / 256, 256>>>(W0, W1, W2, W3, W4, W5);

    cudaFuncSetAttribute(nrc_mma_kernel,
                         cudaFuncAttributeMaxDynamicSharedMemorySize, SM_TOTAL);
    const int grid = (B + CTA_PTS - 1) / CTA_PTS;
    nrc_mma_kernel<<<grid, NTHREADS, SM_TOTAL>>>(p, wi, nrm, alpha, beta, r, W6,
                                                 (float*)d_out, B);
}

// round 15
// speedup vs baseline: 7.4689x; 1.1905x over previous
#include <cuda_runtime.h>
#include <cuda_fp16.h>
#include <cstdint>

#define NTHREADS 512                // 16 warps, m=32 per warp
#define CTA_PTS  512
#define WSTRIDE  72                 // fp16 elems per weight/staging row (64 + 8 pad)
#define ROWB     (WSTRIDE * 2)      // 144 bytes per row
#define WMAT_B   (64 * ROWB)        // 9216 B per 64x64 fp16 matrix

// ---- SMEM layout (bytes) --------------------------------------------------
#define OFF_W    0                  // 6 fp16 weight matrices = 55296 B
#define OFF_A    (6 * WMAT_B)       // A staging [512][72] fp16 = 73728 B
#define A_BYTES  (CTA_PTS * ROWB)
#define OFF_W6   (OFF_A + A_BYTES)  // 192 floats
#define SM_TOTAL (OFF_W6 + 768)     // 129792 B

// ---- Device scratch: fp16 padded weights ----------------------------------
__device__ __align__(16) unsigned char g_Wb[6 * WMAT_B];

__global__ void prep_weights(const float* __restrict__ W0, const float* __restrict__ W1,
                             const float* __restrict__ W2, const float* __restrict__ W3,
                             const float* __restrict__ W4, const float* __restrict__ W5) {
    int i = blockIdx.x * blockDim.x + threadIdx.x;
    if (i >= 6 * 4096) return;
    int l = i >> 12, j = (i >> 6) & 63, k = i & 63;
    const float* W;
    switch (l) {
        case 0: W = W0; break; case 1: W = W1; break; case 2: W = W2; break;
        case 3: W = W3; break; case 4: W = W4; break; default: W = W5; break;
    }
    ((__half*)g_Wb)[(l * 64 + j) * WSTRIDE + k] = __float2half_rn(W[j * 64 + k]);
}

// ---- warp-level MMA helpers (baseline PTX, no sm_103a features) -----------
__device__ __forceinline__ uint32_t smem_u32(const void* p) {
    uint32_t a;
    asm("{ .reg .u64 t; cvta.to.shared.u64 t, %1; cvt.u32.u64 %0, t; }" : "=r"(a) : "l"(p));
    return a;
}
__device__ __forceinline__ void ldsm4(uint32_t& r0, uint32_t& r1, uint32_t& r2, uint32_t& r3,
                                      uint32_t addr) {
    asm volatile("ldmatrix.sync.aligned.m8n8.x4.shared.b16 {%0,%1,%2,%3}, [%4];"
                 : "=r"(r0), "=r"(r1), "=r"(r2), "=r"(r3) : "r"(addr));
}
__device__ __forceinline__ void mma16816(float* c, const uint32_t* a, uint32_t b0, uint32_t b1) {
    asm volatile("mma.sync.aligned.m16n8k16.row.col.f32.f16.f16.f32 "
                 "{%0,%1,%2,%3}, {%4,%5,%6,%7}, {%8,%9}, {%0,%1,%2,%3};"
                 : "+f"(c[0]), "+f"(c[1]), "+f"(c[2]), "+f"(c[3])
                 : "r"(a[0]), "r"(a[1]), "r"(a[2]), "r"(a[3]), "r"(b0), "r"(b1));
}
__device__ __forceinline__ uint32_t packh(float lo, float hi) {
    __half2 t = __floats2half2_rn(lo, hi);              // .x = lower 16 bits
    return *(uint32_t*)&t;
}
// fused ReLU + fp32x2 -> fp16x2 pack (lo -> lower 16 bits)
__device__ __forceinline__ uint32_t relu_packh(float lo, float hi) {
    uint32_t r;
    asm("cvt.rn.relu.f16x2.f32 %0, %1, %2;" : "=r"(r) : "f"(hi), "f"(lo));
    return r;
}

// ---------------------------------------------------------------------------
// Persistent fully-fused kernel: one CTA per SM loops over point tiles.
// Weights staged ONCE; A staging is warp-local (thread t writes row t, warp w
// ldsm-reads rows 32w..32w+31) so the tile loop has NO CTA barrier — warps
// free-run and decorrelate, overlapping encode with other warps' MMAs.
// Per tile: encode -> STS -> syncwarp -> 6 fp16 HMMA layers (fp32 accum,
// fused relu-pack epilogue, activations register-resident) -> fp32 final.
// ---------------------------------------------------------------------------
__global__ __launch_bounds__(NTHREADS, 1)
void nrc_mma_kernel(const float* __restrict__ gp,    const float* __restrict__ gwi,
                    const float* __restrict__ gn,    const float* __restrict__ galpha,
                    const float* __restrict__ gbeta, const float* __restrict__ gr,
                    const float* __restrict__ gW6,   float* __restrict__ gout,
                    int ntiles, int B)
{
    extern __shared__ __align__(16) char smem[];
    const int tid  = threadIdx.x;
    const int lane = tid & 31;
    const int warp = tid >> 5;

    // ---- stage weights (55296 B = 3456 float4) + W6, once per CTA
    {
        const float4* src = (const float4*)g_Wb;
        float4*       dst = (float4*)(smem + OFF_W);
        #pragma unroll
        for (int j = 0; j < 7; j++) {
            int idx = tid + j * NTHREADS;
            if (idx < 3456) dst[idx] = src[idx];
        }
        if (tid < 192) ((float*)(smem + OFF_W6))[tid] = gW6[tid];
    }
    __syncthreads();                               // the ONLY CTA barrier

    // ---- per-lane ldmatrix address components (loop-invariant)
    const uint32_t smb  = smem_u32(smem);
    const int rit = lane & 7;
    const uint32_t laneA = ((uint32_t)(rit + ((lane >> 3) & 1) * 8) * ROWB) + ((lane >> 4) & 1) * 16;
    const uint32_t laneB = ((uint32_t)(rit + ((lane >> 4) & 1) * 8) * ROWB) + ((lane >> 3) & 1) * 16;
    const int wrb = warp * 32;                     // warp's first staging row
    const uint32_t abA  = smb + OFF_A + (uint32_t)wrb * ROWB + laneA;
    char* stage = smem + OFF_A + tid * ROWB;
    const float* W6s = (const float*)(smem + OFF_W6);
    const int g   = lane >> 2;
    const int tig = lane & 3;

    for (int t = blockIdx.x; t < ntiles; t += gridDim.x) {
        // ---- encode one point -> f[64] in registers
        const int id  = t * CTA_PTS + tid;
        const int idc = (id < B) ? id : (B - 1);
        const int id3 = idc * 3;
        {
            const float PI = 3.14159265358979323846f;
            float f[64];
            #pragma unroll
            for (int d = 0; d < 3; d++) {
                float a = PI * gp[id3 + d];
                float s, c;
                sincosf(a, &s, &c);
                f[d * 12 + 0] = s;
                f[d * 12 + 6] = c;
                #pragma unroll
                for (int fq = 1; fq < 6; fq++) {
                    float s2 = 2.0f * s * c;
                    float c2 = c * c - s * s;
                    s = s2; c = c2;
                    f[d * 12 + fq]     = s;
                    f[d * 12 + 6 + fq] = c;
                }
            }
            #pragma unroll
            for (int which = 0; which < 2; which++) {
                const float* s3 = which ? gn : gwi;
                const int off = 36 + which * 8;
                float x = s3[id3], y = s3[id3 + 1], z = s3[id3 + 2];
                float nn = sqrtf(x * x + y * y + z * z) + 1e-8f;
                float u  = atan2f(y, x) * 0.15915494309189535f + 0.5f;
                float zn = z / nn;
                zn = fminf(fmaxf(zn, -1.0f + 1e-6f), 1.0f - 1e-6f);
                float v  = acosf(zn) * 0.3183098861837907f;
                #pragma unroll
                for (int i = 0; i < 4; i++) {
                    float c  = 0.125f + 0.25f * (float)i;
                    float t0 = (u - c) * 4.0f;
                    float t1 = (v - c) * 4.0f;
                    f[off + i]     = __expf(-0.5f * t0 * t0);
                    f[off + 4 + i] = __expf(-0.5f * t1 * t1);
                }
            }
            {
                float xr = 1.0f - __expf(-gr[idc]);
                #pragma unroll
                for (int i = 0; i < 4; i++) {
                    float c = 0.125f + 0.25f * (float)i;
                    float tt = (xr - c) * 4.0f;
                    f[52 + i] = __expf(-0.5f * tt * tt);
                }
            }
            f[56] = galpha[id3]; f[57] = galpha[id3 + 1]; f[58] = galpha[id3 + 2];
            f[59] = gbeta[id3];  f[60] = gbeta[id3 + 1];  f[61] = gbeta[id3 + 2];
            f[62] = 1.0f; f[63] = 1.0f;

            // pack + batched STS.128 into this thread's own staging row
            #pragma unroll
            for (int ch = 0; ch < 8; ch++) {
                uint4 v;
                v.x = packh(f[ch * 8 + 0], f[ch * 8 + 1]);
                v.y = packh(f[ch * 8 + 2], f[ch * 8 + 3]);
                v.z = packh(f[ch * 8 + 4], f[ch * 8 + 5]);
                v.w = packh(f[ch * 8 + 6], f[ch * 8 + 7]);
                *(uint4*)(stage + ch * 16) = v;
            }
        }
        __syncwarp();                              // staging rows are warp-local

        // ---- load layer-0 A fragments (2 m16 tiles per k-block)
        uint32_t Ah[4][8];                         // [k-block][mt*4 + reg]
        #pragma unroll
        for (int kb = 0; kb < 4; kb++)
            #pragma unroll
            for (int mt = 0; mt < 2; mt++)
                ldsm4(Ah[kb][4 * mt], Ah[kb][4 * mt + 1],
                      Ah[kb][4 * mt + 2], Ah[kb][4 * mt + 3],
                      abA + mt * 16 * ROWB + kb * 32);

        float C[8][8];                             // [n-block][mt*4 + reg]
        #pragma unroll
        for (int l = 0; l < 6; l++) {
            #pragma unroll
            for (int nb = 0; nb < 8; nb++)
                #pragma unroll
                for (int i = 0; i < 8; i++) C[nb][i] = 0.0f;

            const uint32_t wmat = smb + OFF_W + (uint32_t)l * WMAT_B + laneB;
            #pragma unroll
            for (int kb = 0; kb < 4; kb++) {
                uint32_t Wf[4][4];
                #pragma unroll
                for (int np = 0; np < 4; np++)
                    ldsm4(Wf[np][0], Wf[np][1], Wf[np][2], Wf[np][3],
                          wmat + (uint32_t)np * (16 * ROWB) + kb * 32);
                #pragma unroll
                for (int np = 0; np < 4; np++)
                    #pragma unroll
                    for (int mt = 0; mt < 2; mt++) {
                        mma16816(&C[2 * np][4 * mt],     &Ah[kb][4 * mt], Wf[np][0], Wf[np][1]);
                        mma16816(&C[2 * np + 1][4 * mt], &Ah[kb][4 * mt], Wf[np][2], Wf[np][3]);
                    }
            }

            if (l < 5) {
                // fused ReLU + pack: C-frag (two n8 blocks) == next A-frag
                #pragma unroll
                for (int kb = 0; kb < 4; kb++)
                    #pragma unroll
                    for (int mt = 0; mt < 2; mt++) {
                        const float* c0 = &C[2 * kb][4 * mt];
                        const float* c1 = &C[2 * kb + 1][4 * mt];
                        #pragma unroll
                        for (int h = 0; h < 2; h++) {  // h=0: row g, h=1: row g+8
                            Ah[kb][4 * mt + h]     = relu_packh(c0[2 * h], c0[2 * h + 1]);
                            Ah[kb][4 * mt + 2 + h] = relu_packh(c1[2 * h], c1[2 * h + 1]);
                        }
                    }
            } else {
                // last hidden layer: fp32 ReLU (final matmul is exact fp32)
                #pragma unroll
                for (int nb = 0; nb < 8; nb++)
                    #pragma unroll
                    for (int i = 0; i < 8; i++) C[nb][i] = fmaxf(C[nb][i], 0.0f);
            }
        }

        // ---- final layer 64->3 in exact fp32 from C fragments
        float o[4][3];
        #pragma unroll
        for (int s = 0; s < 4; s++) { o[s][0] = 0.f; o[s][1] = 0.f; o[s][2] = 0.f; }
        #pragma unroll
        for (int nb = 0; nb < 8; nb++) {
            const int k0 = nb * 8 + 2 * tig;
            #pragma unroll
            for (int mt = 0; mt < 2; mt++) {
                float v0 = C[nb][4 * mt + 0], v1 = C[nb][4 * mt + 1];
                float v2 = C[nb][4 * mt + 2], v3 = C[nb][4 * mt + 3];
                #pragma unroll
                for (int i = 0; i < 3; i++) {
                    float w0 = W6s[i * 64 + k0], w1 = W6s[i * 64 + k0 + 1];
                    o[2 * mt][i]     += v0 * w0 + v1 * w1;
                    o[2 * mt + 1][i] += v2 * w0 + v3 * w1;
                }
            }
        }
        #pragma unroll
        for (int s = 0; s < 4; s++)
            #pragma unroll
            for (int i = 0; i < 3; i++) {
                o[s][i] += __shfl_xor_sync(0xFFFFFFFFu, o[s][i], 1);
                o[s][i] += __shfl_xor_sync(0xFFFFFFFFu, o[s][i], 2);
            }
        if (tig == 0) {
            #pragma unroll
            for (int s = 0; s < 4; s++) {
                int row = wrb + g + 16 * (s >> 1) + 8 * (s & 1);
                int idp = t * CTA_PTS + row;
                if (idp < B) {
                    int i3 = idp * 3;
                    #pragma unroll
                    for (int i = 0; i < 3; i++)
                        gout[i3 + i] = o[s][i] * (galpha[i3 + i] + gbeta[i3 + i]);
                }
            }
        }
    }
}

// ---------------------------------------------------------------------------
extern "C" void kernel_launch(void* const* d_in, const int* in_sizes, int n_in,
                              void* d_out, int out_size) {
    const float* p     = (const float*)d_in[0];
    const float* wi    = (const float*)d_in[1];
    const float* nrm   = (const float*)d_in[2];
    const float* alpha = (const float*)d_in[3];
    const float* beta  = (const float*)d_in[4];
    const float* r     = (const float*)d_in[5];
    const float* W0    = (const float*)d_in[6];
    const float* W1    = (const float*)d_in[7];
    const float* W2    = (const float*)d_in[8];
    const float* W3    = (const float*)d_in[9];
    const float* W4    = (const float*)d_in[10];
    const float* W5    = (const float*)d_in[11];
    const float* W6    = (const float*)d_in[12];

    const int B = in_sizes[0] / 3;
    const int ntiles = (B + CTA_PTS - 1) / CTA_PTS;

    prep_weights<<<(6 * 4096 + 255) / 256, 256>>>(W0, W1, W2, W3, W4, W5);

    static int nsm = 0;
    if (nsm == 0) {
        int dev = 0;
        cudaGetDevice(&dev);
        cudaDeviceGetAttribute(&nsm, cudaDevAttrMultiProcessorCount, dev);
        if (nsm <= 0) nsm = 148;
        cudaFuncSetAttribute(nrc_mma_kernel,
                             cudaFuncAttributeMaxDynamicSharedMemorySize, SM_TOTAL);
    }
    const int grid = (ntiles < nsm) ? ntiles : nsm;
    nrc_mma_kernel<<<grid, NTHREADS, SM_TOTAL>>>(p, wi, nrm, alpha, beta, r, W6,
                                                 (float*)d_out, ntiles, B);
}